// round 1
// baseline (speedup 1.0000x reference)
#include <cuda_runtime.h>
#include <math.h>

#define SEQ    2048
#define DM     1024
#define NH     16
#define HD     64
#define BATCH  2
#define MTOT   (BATCH*SEQ)   // 4096

// Scratch (allocation-free rule: __device__ globals)
__device__ float g_Qp[MTOT*DM];
__device__ float g_Kp[MTOT*DM];
__device__ float g_Vp[MTOT*DM];
__device__ float g_ctx[MTOT*DM];

// ---------------------------------------------------------------------------
// C[M,N] = A[M,K] @ W[K,N] + bias,  M=4096, N=K=1024 (fixed shapes)
// 128x128 block tile, BK=8, 256 threads, 8x8 per-thread microtile.
// ---------------------------------------------------------------------------
__global__ __launch_bounds__(256) void gemm_bias_kernel(
    const float* __restrict__ A, const float* __restrict__ W,
    const float* __restrict__ bias, float* __restrict__ C)
{
    __shared__ float As[8][132];   // stored transposed: As[k][m]
    __shared__ float Ws[8][132];   // Ws[k][n]

    const int tid = threadIdx.x;
    const int tx  = tid & 15;      // 16 cols of threads
    const int ty  = tid >> 4;      // 16 rows of threads
    const long bm = (long)blockIdx.y * 128;
    const int  bn = blockIdx.x * 128;

    const int arow = tid >> 1;          // 0..127
    const int acol = (tid & 1) << 2;    // 0 or 4
    const int wrow = tid >> 5;          // 0..7
    const int wcol = (tid & 31) << 2;   // 0..124

    const float* Ap = A + (bm + arow) * DM + acol;
    const float* Wp = W + (long)wrow * DM + bn + wcol;

    float acc[8][8];
#pragma unroll
    for (int i = 0; i < 8; i++)
#pragma unroll
        for (int j = 0; j < 8; j++) acc[i][j] = 0.f;

    for (int k0 = 0; k0 < DM; k0 += 8) {
        float4 av = *(const float4*)(Ap + k0);
        float4 wv = *(const float4*)(Wp + (long)k0 * DM);
        __syncthreads();   // previous iteration's frag reads done
        As[acol + 0][arow] = av.x;
        As[acol + 1][arow] = av.y;
        As[acol + 2][arow] = av.z;
        As[acol + 3][arow] = av.w;
        *(float4*)&Ws[wrow][wcol] = wv;
        __syncthreads();
#pragma unroll
        for (int k = 0; k < 8; k++) {
            float a[8], b[8];
            *(float4*)&a[0] = *(const float4*)&As[k][ty * 8];
            *(float4*)&a[4] = *(const float4*)&As[k][ty * 8 + 4];
            *(float4*)&b[0] = *(const float4*)&Ws[k][tx * 8];
            *(float4*)&b[4] = *(const float4*)&Ws[k][tx * 8 + 4];
#pragma unroll
            for (int i = 0; i < 8; i++)
#pragma unroll
                for (int j = 0; j < 8; j++)
                    acc[i][j] += a[i] * b[j];
        }
    }

#pragma unroll
    for (int i = 0; i < 8; i++) {
        long row = bm + ty * 8 + i;
#pragma unroll
        for (int j = 0; j < 8; j += 4) {
            int col = bn + tx * 8 + j;
            float4 v;
            v.x = acc[i][j + 0] + bias[col + 0];
            v.y = acc[i][j + 1] + bias[col + 1];
            v.z = acc[i][j + 2] + bias[col + 2];
            v.w = acc[i][j + 3] + bias[col + 3];
            *(float4*)&C[row * DM + col] = v;
        }
    }
}

// ---------------------------------------------------------------------------
// Flash attention, fp32. grid = (SEQ/64, B*NH), 128 threads.
// Per block: 64 query rows of one head; loop over 32 K/V tiles of 64.
// Thread layout: tx = tid&7 (8), ty = tid>>3 (16). Microtile 4 rows x 8 cols.
// ---------------------------------------------------------------------------
#define PADA 68   // row stride (floats), multiple of 4 for float4 frags

__global__ __launch_bounds__(128) void attn_kernel(
    const float* __restrict__ Qg, const float* __restrict__ Kg,
    const float* __restrict__ Vg, float* __restrict__ Og)
{
    extern __shared__ float sm[];
    float* Qts = sm;                  // [64][PADA], transposed: Qts[k][r]
    float* Kts = sm + 64 * PADA;      // transposed: Kts[k][c]
    float* Pts = sm + 2 * 64 * PADA;  // transposed: Pts[c][r]
    float* Vs  = sm + 3 * 64 * PADA;  // natural:    Vs[c][d]

    const int tid = threadIdx.x;
    const int tx  = tid & 7;
    const int ty  = tid >> 3;
    const int b   = blockIdx.y >> 4;
    const int h   = blockIdx.y & 15;
    const int q0  = blockIdx.x * 64;

    const float* Qbase = Qg + ((long)b * SEQ + q0) * DM + h * HD;
    const float* Kbase = Kg + (long)b * SEQ * DM + h * HD;
    const float* Vbase = Vg + (long)b * SEQ * DM + h * HD;

    // Load Q tile transposed
    for (int idx = tid; idx < 64 * 64; idx += 128) {
        int r = idx >> 6, k = idx & 63;
        Qts[k * PADA + r] = Qbase[(long)r * DM + k];
    }

    float m[4], l[4], o[4][8];
#pragma unroll
    for (int i = 0; i < 4; i++) {
        m[i] = -INFINITY; l[i] = 0.f;
#pragma unroll
        for (int j = 0; j < 8; j++) o[i][j] = 0.f;
    }

    for (int t = 0; t < SEQ / 64; ++t) {
        const float* Kt = Kbase + (long)t * 64 * DM;
        const float* Vt = Vbase + (long)t * 64 * DM;
        __syncthreads();   // previous tile's PV reads done (also covers Q load)
        for (int idx = tid; idx < 64 * 64; idx += 128) {
            int r = idx >> 6, k = idx & 63;
            Kts[k * PADA + r] = Kt[(long)r * DM + k];
            Vs[r * PADA + k]  = Vt[(long)r * DM + k];
        }
        __syncthreads();

        // S = (Q K^T) * scale, 4x8 per thread
        float s[4][8];
#pragma unroll
        for (int i = 0; i < 4; i++)
#pragma unroll
            for (int j = 0; j < 8; j++) s[i][j] = 0.f;

#pragma unroll 8
        for (int k = 0; k < 64; k++) {
            float a[4], bb[8];
            *(float4*)&a[0]  = *(const float4*)&Qts[k * PADA + ty * 4];
            *(float4*)&bb[0] = *(const float4*)&Kts[k * PADA + tx * 8];
            *(float4*)&bb[4] = *(const float4*)&Kts[k * PADA + tx * 8 + 4];
#pragma unroll
            for (int i = 0; i < 4; i++)
#pragma unroll
                for (int j = 0; j < 8; j++)
                    s[i][j] += a[i] * bb[j];
        }

        // Online softmax (rows live in 8-lane groups: lanes ty*8+tx)
#pragma unroll
        for (int i = 0; i < 4; i++) {
            float mx = -INFINITY;
#pragma unroll
            for (int j = 0; j < 8; j++) {
                s[i][j] *= 0.125f;               // 1/sqrt(64)
                mx = fmaxf(mx, s[i][j]);
            }
            mx = fmaxf(mx, __shfl_xor_sync(0xffffffffu, mx, 1));
            mx = fmaxf(mx, __shfl_xor_sync(0xffffffffu, mx, 2));
            mx = fmaxf(mx, __shfl_xor_sync(0xffffffffu, mx, 4));
            float mnew = fmaxf(m[i], mx);
            float corr = __expf(m[i] - mnew);    // 0 if m[i] == -inf
            m[i] = mnew;
            float rs = 0.f;
#pragma unroll
            for (int j = 0; j < 8; j++) {
                float p = __expf(s[i][j] - mnew);
                s[i][j] = p;
                rs += p;
            }
            rs += __shfl_xor_sync(0xffffffffu, rs, 1);
            rs += __shfl_xor_sync(0xffffffffu, rs, 2);
            rs += __shfl_xor_sync(0xffffffffu, rs, 4);
            l[i] = l[i] * corr + rs;
#pragma unroll
            for (int j = 0; j < 8; j++) {
                o[i][j] *= corr;
                Pts[(tx * 8 + j) * PADA + ty * 4 + i] = s[i][j];
            }
        }
        __syncthreads();

        // O += P @ V
#pragma unroll 8
        for (int c = 0; c < 64; c++) {
            float a[4], bb[8];
            *(float4*)&a[0]  = *(const float4*)&Pts[c * PADA + ty * 4];
            *(float4*)&bb[0] = *(const float4*)&Vs[c * PADA + tx * 8];
            *(float4*)&bb[4] = *(const float4*)&Vs[c * PADA + tx * 8 + 4];
#pragma unroll
            for (int i = 0; i < 4; i++)
#pragma unroll
                for (int j = 0; j < 8; j++)
                    o[i][j] += a[i] * bb[j];
        }
    }

#pragma unroll
    for (int i = 0; i < 4; i++) {
        float inv = 1.f / l[i];
        long row = (long)b * SEQ + q0 + ty * 4 + i;
        float4 v0, v1;
        v0.x = o[i][0] * inv; v0.y = o[i][1] * inv;
        v0.z = o[i][2] * inv; v0.w = o[i][3] * inv;
        v1.x = o[i][4] * inv; v1.y = o[i][5] * inv;
        v1.z = o[i][6] * inv; v1.w = o[i][7] * inv;
        *(float4*)&Og[row * DM + h * HD + tx * 8]     = v0;
        *(float4*)&Og[row * DM + h * HD + tx * 8 + 4] = v1;
    }
}

// ---------------------------------------------------------------------------
extern "C" void kernel_launch(void* const* d_in, const int* in_sizes, int n_in,
                              void* d_out, int out_size)
{
    const float* query = (const float*)d_in[0];
    const float* key_  = (const float*)d_in[1];
    const float* value = (const float*)d_in[2];
    const float* Wq    = (const float*)d_in[3];
    const float* bq    = (const float*)d_in[4];
    const float* Wk    = (const float*)d_in[5];
    const float* bk    = (const float*)d_in[6];
    const float* Wv    = (const float*)d_in[7];
    const float* bv    = (const float*)d_in[8];
    const float* Wo    = (const float*)d_in[9];
    const float* bo    = (const float*)d_in[10];

    float *qp, *kp, *vp, *ctx;
    cudaGetSymbolAddress((void**)&qp,  g_Qp);
    cudaGetSymbolAddress((void**)&kp,  g_Kp);
    cudaGetSymbolAddress((void**)&vp,  g_Vp);
    cudaGetSymbolAddress((void**)&ctx, g_ctx);

    dim3 ggrid(DM / 128, MTOT / 128);  // (8, 32)

    gemm_bias_kernel<<<ggrid, 256>>>(query, Wq, bq, qp);
    gemm_bias_kernel<<<ggrid, 256>>>(key_,  Wk, bk, kp);
    gemm_bias_kernel<<<ggrid, 256>>>(value, Wv, bv, vp);

    const int smem_bytes = 4 * 64 * PADA * sizeof(float);  // 69632
    cudaFuncSetAttribute(attn_kernel,
                         cudaFuncAttributeMaxDynamicSharedMemorySize, smem_bytes);
    dim3 agrid(SEQ / 64, BATCH * NH);  // (32, 32)
    attn_kernel<<<agrid, 128, smem_bytes>>>(qp, kp, vp, ctx);

    gemm_bias_kernel<<<ggrid, 256>>>(ctx, Wo, bo, (float*)d_out);
}

// round 3
// speedup vs baseline: 1.6608x; 1.6608x over previous
#include <cuda_runtime.h>
#include <cuda_bf16.h>
#include <cstdint>
#include <math.h>

#define SEQ    2048
#define DM     1024
#define NH     16
#define HD     64
#define BATCH  2
#define MTOT   (BATCH*SEQ)   // 4096

// ---------------------------------------------------------------------------
// Scratch (__device__ globals; allocation-free rule)
// ---------------------------------------------------------------------------
__device__ float g_Qp[MTOT*DM];
__device__ float g_Kp[MTOT*DM];
__device__ float g_Vp[MTOT*DM];
__device__ float g_ctx[MTOT*DM];
__device__ __nv_bfloat16 g_Ah[MTOT*DM];
__device__ __nv_bfloat16 g_Al[MTOT*DM];
__device__ __nv_bfloat16 g_Wh[DM*DM];
__device__ __nv_bfloat16 g_Wl[DM*DM];

// ---------------------------------------------------------------------------
// mma.sync helpers (baseline PTX — works on compute_103 target)
// ---------------------------------------------------------------------------
__device__ __forceinline__ uint32_t smem_to_u32(const void* smem_ptr) {
    uint32_t addr;
    asm("{ .reg .u64 tmp; cvta.to.shared.u64 tmp, %1; cvt.u32.u64 %0, tmp; }"
        : "=r"(addr) : "l"(smem_ptr));
    return addr;
}

__device__ __forceinline__ void mma16816(float* c, const uint32_t* a, const uint32_t* b) {
    asm volatile(
        "mma.sync.aligned.m16n8k16.row.col.f32.bf16.bf16.f32 "
        "{%0,%1,%2,%3}, {%4,%5,%6,%7}, {%8,%9}, {%0,%1,%2,%3};"
        : "+f"(c[0]), "+f"(c[1]), "+f"(c[2]), "+f"(c[3])
        : "r"(a[0]), "r"(a[1]), "r"(a[2]), "r"(a[3]), "r"(b[0]), "r"(b[1]));
}

// A fragment: 16x16 bf16 from smem tile with 128B rows, chunk swizzle c^(row&7)
__device__ __forceinline__ void ldmA(uint32_t* f, uint32_t tile, int row0, int chunk0, int lane) {
    int row = row0 + (lane & 15);
    int c   = chunk0 + (lane >> 4);
    uint32_t addr = tile + row * 128 + ((c ^ (row & 7)) << 4);
    asm volatile("ldmatrix.sync.aligned.m8n8.x4.shared.b16 {%0,%1,%2,%3}, [%4];"
        : "=r"(f[0]), "=r"(f[1]), "=r"(f[2]), "=r"(f[3]) : "r"(addr));
}

// B fragment: 8(n)x16(k) from K-major [n][k] tile
__device__ __forceinline__ void ldmB(uint32_t* f, uint32_t tile, int row0, int chunk0, int lane) {
    int row = row0 + (lane & 7);
    int c   = chunk0 + ((lane >> 3) & 1);
    uint32_t addr = tile + row * 128 + ((c ^ (row & 7)) << 4);
    asm volatile("ldmatrix.sync.aligned.m8n8.x2.shared.b16 {%0,%1}, [%2];"
        : "=r"(f[0]), "=r"(f[1]) : "r"(addr));
}

// ---------------------------------------------------------------------------
// Conversion kernels: fp32 -> bf16 hi/lo split (a = hi + lo, ~16 mantissa bits)
// ---------------------------------------------------------------------------
__global__ void conv_hilo_kernel(const float* __restrict__ in,
                                 __nv_bfloat16* __restrict__ hi,
                                 __nv_bfloat16* __restrict__ lo, int n4)
{
    int i = blockIdx.x * blockDim.x + threadIdx.x;
    if (i >= n4) return;
    float4 v = reinterpret_cast<const float4*>(in)[i];
    __nv_bfloat16 h0 = __float2bfloat16(v.x);
    __nv_bfloat16 h1 = __float2bfloat16(v.y);
    __nv_bfloat16 h2 = __float2bfloat16(v.z);
    __nv_bfloat16 h3 = __float2bfloat16(v.w);
    __nv_bfloat16 l0 = __float2bfloat16(v.x - __bfloat162float(h0));
    __nv_bfloat16 l1 = __float2bfloat16(v.y - __bfloat162float(h1));
    __nv_bfloat16 l2 = __float2bfloat16(v.z - __bfloat162float(h2));
    __nv_bfloat16 l3 = __float2bfloat16(v.w - __bfloat162float(h3));
    __nv_bfloat162* hp = reinterpret_cast<__nv_bfloat162*>(hi);
    __nv_bfloat162* lp = reinterpret_cast<__nv_bfloat162*>(lo);
    hp[2*i]   = __nv_bfloat162(h0, h1);
    hp[2*i+1] = __nv_bfloat162(h2, h3);
    lp[2*i]   = __nv_bfloat162(l0, l1);
    lp[2*i+1] = __nv_bfloat162(l2, l3);
}

// W[K][N] fp32 -> Wt_hi/Wt_lo [N][K] bf16 (transpose + split)
__global__ void wconv_kernel(const float* __restrict__ W,
                             __nv_bfloat16* __restrict__ th,
                             __nv_bfloat16* __restrict__ tl)
{
    __shared__ float t[32][33];
    int tx = threadIdx.x, ty = threadIdx.y;       // (32, 8)
    int n0 = blockIdx.x * 32, k0 = blockIdx.y * 32;
#pragma unroll
    for (int j = 0; j < 32; j += 8)
        t[ty + j][tx] = W[(long)(k0 + ty + j) * DM + n0 + tx];
    __syncthreads();
#pragma unroll
    for (int j = 0; j < 32; j += 8) {
        float x = t[tx][ty + j];                  // (k_local=tx, n_local=ty+j)
        long n = n0 + ty + j, k = k0 + tx;
        __nv_bfloat16 h = __float2bfloat16(x);
        th[n * DM + k] = h;
        tl[n * DM + k] = __float2bfloat16(x - __bfloat162float(h));
    }
}

// ---------------------------------------------------------------------------
// mma.sync bf16x3 GEMM: C[M,N] = (Ah+Al)[M,K] * ((Bh+Bl)[N,K])^T + bias
// BM=128, BN=128, BK=32; 256 threads = 8 warps (2x4), warp tile 64x32.
// Smem tile row layout: 128B = [32 bf16 hi | 32 bf16 lo], chunk swizzle.
// Double buffered (2 x 32KB).
// ---------------------------------------------------------------------------
#define GBM 128
#define GBN 128
#define GBK 32
#define NCHUNK (DM / GBK)          // 32
#define TILEB  (128 * 128)         // 16KB per (A or B) buffer
#define GEMM_SMEM (4 * TILEB)      // 65536

__device__ __forceinline__ void stsw(char* tile, int row, int c, uint4 v) {
    uint32_t off = (uint32_t)(row * 128 + ((c ^ (row & 7)) << 4));
    *reinterpret_cast<uint4*>(tile + off) = v;
}

__global__ __launch_bounds__(256, 1) void gemm_tc_kernel(
    const __nv_bfloat16* __restrict__ Ah, const __nv_bfloat16* __restrict__ Al,
    const __nv_bfloat16* __restrict__ Bh, const __nv_bfloat16* __restrict__ Bl,
    const float* __restrict__ bias, float* __restrict__ C)
{
    extern __shared__ char gsm[];
    const uint32_t sbase = smem_to_u32(gsm);
    const int tid  = threadIdx.x;
    const int wid  = tid >> 5;
    const int lane = tid & 31;
    const int wm   = (wid >> 2) * 64;     // 0 / 64
    const int wn   = (wid & 3) * 32;      // 0..96
    const long bm  = (long)blockIdx.y * GBM;
    const int  bn  = blockIdx.x * GBN;

    const int urow = tid >> 2;            // 0..63  (rows tid>>2 and +64)
    const int uc   = tid & 3;             // 16B chunk 0..3

    float acc[4][4][4];
#pragma unroll
    for (int mi = 0; mi < 4; mi++)
#pragma unroll
        for (int ni = 0; ni < 4; ni++)
#pragma unroll
            for (int q = 0; q < 4; q++) acc[mi][ni][q] = 0.f;

    // Preload chunk 0 into buffer 0
    {
        char* bA = gsm;
        char* bB = gsm + TILEB;
#pragma unroll
        for (int t = 0; t < 2; t++) {
            int row = urow + t * 64;
            const long go = (bm + row) * DM + uc * 8;
            const long gn = ((long)bn + row) * DM + uc * 8;
            stsw(bA, row, uc,     *(const uint4*)(Ah + go));
            stsw(bA, row, uc + 4, *(const uint4*)(Al + go));
            stsw(bB, row, uc,     *(const uint4*)(Bh + gn));
            stsw(bB, row, uc + 4, *(const uint4*)(Bl + gn));
        }
    }
    __syncthreads();

    for (int it = 0; it < NCHUNK; ++it) {
        const int buf = it & 1;
        const uint32_t sA = sbase + buf * 2 * TILEB;
        const uint32_t sB = sA + TILEB;

        // Prefetch next chunk from gmem into registers
        uint4 pAh[2], pAl[2], pBh[2], pBl[2];
        if (it + 1 < NCHUNK) {
            const int k0 = (it + 1) * GBK;
#pragma unroll
            for (int t = 0; t < 2; t++) {
                int row = urow + t * 64;
                const long go = (bm + row) * DM + k0 + uc * 8;
                const long gn = ((long)bn + row) * DM + k0 + uc * 8;
                pAh[t] = *(const uint4*)(Ah + go);
                pAl[t] = *(const uint4*)(Al + go);
                pBh[t] = *(const uint4*)(Bh + gn);
                pBl[t] = *(const uint4*)(Bl + gn);
            }
        }

        // MMA on current buffer
#pragma unroll
        for (int ks = 0; ks < 2; ks++) {
            uint32_t afh[4][4], afl[4][4];
#pragma unroll
            for (int mi = 0; mi < 4; mi++) {
                ldmA(afh[mi], sA, wm + mi * 16, ks * 2,     lane);
                ldmA(afl[mi], sA, wm + mi * 16, ks * 2 + 4, lane);
            }
            uint32_t bfh[4][2], bfl[4][2];
#pragma unroll
            for (int ni = 0; ni < 4; ni++) {
                ldmB(bfh[ni], sB, wn + ni * 8, ks * 2,     lane);
                ldmB(bfl[ni], sB, wn + ni * 8, ks * 2 + 4, lane);
            }
#pragma unroll
            for (int mi = 0; mi < 4; mi++)
#pragma unroll
                for (int ni = 0; ni < 4; ni++) {
                    mma16816(acc[mi][ni], afh[mi], bfh[ni]);
                    mma16816(acc[mi][ni], afh[mi], bfl[ni]);
                    mma16816(acc[mi][ni], afl[mi], bfh[ni]);
                }
        }

        __syncthreads();   // all reads of the other buffer (prev iter) done

        if (it + 1 < NCHUNK) {
            char* bA = gsm + ((it + 1) & 1) * 2 * TILEB;
            char* bB = bA + TILEB;
#pragma unroll
            for (int t = 0; t < 2; t++) {
                int row = urow + t * 64;
                stsw(bA, row, uc,     pAh[t]);
                stsw(bA, row, uc + 4, pAl[t]);
                stsw(bB, row, uc,     pBh[t]);
                stsw(bB, row, uc + 4, pBl[t]);
            }
        }
        __syncthreads();
    }

    // Epilogue: fragment layout m16n8: c0,c1 -> row lane>>2, cols (lane&3)*2(+1); c2,c3 -> row+8
#pragma unroll
    for (int mi = 0; mi < 4; mi++) {
#pragma unroll
        for (int ni = 0; ni < 4; ni++) {
            long r0  = bm + wm + mi * 16 + (lane >> 2);
            int  col = bn + wn + ni * 8 + (lane & 3) * 2;
            float2 bv = *(const float2*)&bias[col];
            float2 v0, v1;
            v0.x = acc[mi][ni][0] + bv.x; v0.y = acc[mi][ni][1] + bv.y;
            v1.x = acc[mi][ni][2] + bv.x; v1.y = acc[mi][ni][3] + bv.y;
            *(float2*)&C[r0 * DM + col]       = v0;
            *(float2*)&C[(r0 + 8) * DM + col] = v1;
        }
    }
}

// ---------------------------------------------------------------------------
// Flash attention, fp32 SIMT. grid = (SEQ/128, B*NH), 128 threads.
// Q tile = 128 rows; microtile 8 rows x 8 cols per thread.
// ---------------------------------------------------------------------------
#define PADK 68    // K/V tile row stride (floats)
#define PADQ 132   // Q/P tile row stride (floats)
#define ATTN_SMEM ((2 * 64 * PADQ + 2 * 64 * PADK) * 4)   // 102400

__global__ __launch_bounds__(128, 1) void attn_kernel(
    const float* __restrict__ Qg, const float* __restrict__ Kg,
    const float* __restrict__ Vg, float* __restrict__ Og)
{
    extern __shared__ float sm[];
    float* Qts = sm;                              // [64 k][PADQ r(128)]
    float* Kts = sm + 64 * PADQ;                  // [64 k][PADK c(64)]
    float* Vs  = sm + 64 * PADQ + 64 * PADK;      // [64 c][PADK d(64)]
    float* Pts = sm + 64 * PADQ + 2 * 64 * PADK;  // [64 c][PADQ r(128)]

    const int tid = threadIdx.x;
    const int tx  = tid & 7;       // 8 col-groups
    const int ty  = tid >> 3;      // 16 row-groups
    const int b   = blockIdx.y >> 4;
    const int h   = blockIdx.y & 15;
    const int q0  = blockIdx.x * 128;

    const float* Qbase = Qg + ((long)b * SEQ + q0) * DM + h * HD;
    const float* Kbase = Kg + (long)b * SEQ * DM + h * HD;
    const float* Vbase = Vg + (long)b * SEQ * DM + h * HD;

    for (int idx = tid; idx < 128 * 64; idx += 128) {
        int r = idx >> 6, k = idx & 63;
        Qts[k * PADQ + r] = Qbase[(long)r * DM + k];
    }

    float m[8], l[8], o[8][8];
#pragma unroll
    for (int i = 0; i < 8; i++) {
        m[i] = -INFINITY; l[i] = 0.f;
#pragma unroll
        for (int j = 0; j < 8; j++) o[i][j] = 0.f;
    }

    for (int t = 0; t < SEQ / 64; ++t) {
        const float* Kt = Kbase + (long)t * 64 * DM;
        const float* Vt = Vbase + (long)t * 64 * DM;
        __syncthreads();
        for (int idx = tid; idx < 64 * 64; idx += 128) {
            int r = idx >> 6, k = idx & 63;
            Kts[k * PADK + r] = Kt[(long)r * DM + k];
            Vs[r * PADK + k]  = Vt[(long)r * DM + k];
        }
        __syncthreads();

        float s[8][8];
#pragma unroll
        for (int i = 0; i < 8; i++)
#pragma unroll
            for (int j = 0; j < 8; j++) s[i][j] = 0.f;

#pragma unroll 4
        for (int k = 0; k < 64; k++) {
            float a[8], bb[8];
            *(float4*)&a[0]  = *(const float4*)&Qts[k * PADQ + ty * 8];
            *(float4*)&a[4]  = *(const float4*)&Qts[k * PADQ + ty * 8 + 4];
            *(float4*)&bb[0] = *(const float4*)&Kts[k * PADK + tx * 8];
            *(float4*)&bb[4] = *(const float4*)&Kts[k * PADK + tx * 8 + 4];
#pragma unroll
            for (int i = 0; i < 8; i++)
#pragma unroll
                for (int j = 0; j < 8; j++)
                    s[i][j] += a[i] * bb[j];
        }

#pragma unroll
        for (int i = 0; i < 8; i++) {
            float mx = -INFINITY;
#pragma unroll
            for (int j = 0; j < 8; j++) {
                s[i][j] *= 0.125f;
                mx = fmaxf(mx, s[i][j]);
            }
            mx = fmaxf(mx, __shfl_xor_sync(0xffffffffu, mx, 1));
            mx = fmaxf(mx, __shfl_xor_sync(0xffffffffu, mx, 2));
            mx = fmaxf(mx, __shfl_xor_sync(0xffffffffu, mx, 4));
            float mnew = fmaxf(m[i], mx);
            float corr = __expf(m[i] - mnew);
            m[i] = mnew;
            float rs = 0.f;
#pragma unroll
            for (int j = 0; j < 8; j++) {
                float p = __expf(s[i][j] - mnew);
                s[i][j] = p;
                rs += p;
            }
            rs += __shfl_xor_sync(0xffffffffu, rs, 1);
            rs += __shfl_xor_sync(0xffffffffu, rs, 2);
            rs += __shfl_xor_sync(0xffffffffu, rs, 4);
            l[i] = l[i] * corr + rs;
#pragma unroll
            for (int j = 0; j < 8; j++) {
                o[i][j] *= corr;
                Pts[(tx * 8 + j) * PADQ + ty * 8 + i] = s[i][j];
            }
        }
        __syncthreads();

#pragma unroll 4
        for (int c = 0; c < 64; c++) {
            float a[8], bb[8];
            *(float4*)&a[0]  = *(const float4*)&Pts[c * PADQ + ty * 8];
            *(float4*)&a[4]  = *(const float4*)&Pts[c * PADQ + ty * 8 + 4];
            *(float4*)&bb[0] = *(const float4*)&Vs[c * PADK + tx * 8];
            *(float4*)&bb[4] = *(const float4*)&Vs[c * PADK + tx * 8 + 4];
#pragma unroll
            for (int i = 0; i < 8; i++)
#pragma unroll
                for (int j = 0; j < 8; j++)
                    o[i][j] += a[i] * bb[j];
        }
    }

#pragma unroll
    for (int i = 0; i < 8; i++) {
        float inv = 1.f / l[i];
        long row = (long)b * SEQ + q0 + ty * 8 + i;
        float4 v0, v1;
        v0.x = o[i][0] * inv; v0.y = o[i][1] * inv;
        v0.z = o[i][2] * inv; v0.w = o[i][3] * inv;
        v1.x = o[i][4] * inv; v1.y = o[i][5] * inv;
        v1.z = o[i][6] * inv; v1.w = o[i][7] * inv;
        *(float4*)&Og[row * DM + h * HD + tx * 8]     = v0;
        *(float4*)&Og[row * DM + h * HD + tx * 8 + 4] = v1;
    }
}

// ---------------------------------------------------------------------------
extern "C" void kernel_launch(void* const* d_in, const int* in_sizes, int n_in,
                              void* d_out, int out_size)
{
    const float* query = (const float*)d_in[0];
    const float* key_  = (const float*)d_in[1];
    const float* value = (const float*)d_in[2];
    const float* Wq    = (const float*)d_in[3];
    const float* bq    = (const float*)d_in[4];
    const float* Wk    = (const float*)d_in[5];
    const float* bk    = (const float*)d_in[6];
    const float* Wv    = (const float*)d_in[7];
    const float* bv    = (const float*)d_in[8];
    const float* Wo    = (const float*)d_in[9];
    const float* bo    = (const float*)d_in[10];

    float *qp, *kp, *vp, *ctx;
    __nv_bfloat16 *ah, *al, *wh, *wl;
    cudaGetSymbolAddress((void**)&qp,  g_Qp);
    cudaGetSymbolAddress((void**)&kp,  g_Kp);
    cudaGetSymbolAddress((void**)&vp,  g_Vp);
    cudaGetSymbolAddress((void**)&ctx, g_ctx);
    cudaGetSymbolAddress((void**)&ah,  g_Ah);
    cudaGetSymbolAddress((void**)&al,  g_Al);
    cudaGetSymbolAddress((void**)&wh,  g_Wh);
    cudaGetSymbolAddress((void**)&wl,  g_Wl);

    cudaFuncSetAttribute(gemm_tc_kernel,
                         cudaFuncAttributeMaxDynamicSharedMemorySize, GEMM_SMEM);
    cudaFuncSetAttribute(attn_kernel,
                         cudaFuncAttributeMaxDynamicSharedMemorySize, ATTN_SMEM);

    const int n4 = MTOT * DM / 4;
    dim3 wgrid(DM / 32, DM / 32);      // (32, 32)
    dim3 wblk(32, 8);
    dim3 ggrid(DM / GBN, MTOT / GBM);  // (8, 32)

    // Q projection
    wconv_kernel<<<wgrid, wblk>>>(Wq, wh, wl);
    conv_hilo_kernel<<<n4 / 256, 256>>>(query, ah, al, n4);
    gemm_tc_kernel<<<ggrid, 256, GEMM_SMEM>>>(ah, al, wh, wl, bq, qp);
    // K projection
    wconv_kernel<<<wgrid, wblk>>>(Wk, wh, wl);
    conv_hilo_kernel<<<n4 / 256, 256>>>(key_, ah, al, n4);
    gemm_tc_kernel<<<ggrid, 256, GEMM_SMEM>>>(ah, al, wh, wl, bk, kp);
    // V projection
    wconv_kernel<<<wgrid, wblk>>>(Wv, wh, wl);
    conv_hilo_kernel<<<n4 / 256, 256>>>(value, ah, al, n4);
    gemm_tc_kernel<<<ggrid, 256, GEMM_SMEM>>>(ah, al, wh, wl, bv, vp);

    // Attention
    dim3 agrid(SEQ / 128, BATCH * NH);  // (16, 32)
    attn_kernel<<<agrid, 128, ATTN_SMEM>>>(qp, kp, vp, ctx);

    // Output projection
    wconv_kernel<<<wgrid, wblk>>>(Wo, wh, wl);
    conv_hilo_kernel<<<n4 / 256, 256>>>(ctx, ah, al, n4);
    gemm_tc_kernel<<<ggrid, 256, GEMM_SMEM>>>(ah, al, wh, wl, bo, (float*)d_out);
}

// round 5
// speedup vs baseline: 3.1908x; 1.9212x over previous
#include <cuda_runtime.h>
#include <cuda_bf16.h>
#include <cstdint>
#include <math.h>

#define SEQ    2048
#define DM     1024
#define NH     16
#define HD     64
#define BATCH  2
#define MTOT   (BATCH*SEQ)   // 4096

// ---------------------------------------------------------------------------
// Scratch (__device__ globals; allocation-free rule)
// ---------------------------------------------------------------------------
__device__ float g_Qp[MTOT*DM];
__device__ float g_Kp[MTOT*DM];
__device__ float g_Vp[MTOT*DM];
__device__ float g_ctx[MTOT*DM];
__device__ __nv_bfloat16 g_Ah[MTOT*DM];
__device__ __nv_bfloat16 g_Al[MTOT*DM];
__device__ __nv_bfloat16 g_Wh[DM*DM];
__device__ __nv_bfloat16 g_Wl[DM*DM];
__device__ __nv_bfloat16 g_Qh[MTOT*DM];
__device__ __nv_bfloat16 g_Ql[MTOT*DM];
__device__ __nv_bfloat16 g_Kh[MTOT*DM];
__device__ __nv_bfloat16 g_Kl[MTOT*DM];
__device__ __nv_bfloat16 g_Vth[MTOT*DM];   // [b][h][d][s]
__device__ __nv_bfloat16 g_Vtl[MTOT*DM];

// ---------------------------------------------------------------------------
// mma.sync helpers (baseline PTX — works on compute_103 target)
// ---------------------------------------------------------------------------
__device__ __forceinline__ uint32_t smem_to_u32(const void* smem_ptr) {
    uint32_t addr;
    asm("{ .reg .u64 tmp; cvta.to.shared.u64 tmp, %1; cvt.u32.u64 %0, tmp; }"
        : "=r"(addr) : "l"(smem_ptr));
    return addr;
}

__device__ __forceinline__ void mma16816(float* c, const uint32_t* a, const uint32_t* b) {
    asm volatile(
        "mma.sync.aligned.m16n8k16.row.col.f32.bf16.bf16.f32 "
        "{%0,%1,%2,%3}, {%4,%5,%6,%7}, {%8,%9}, {%0,%1,%2,%3};"
        : "+f"(c[0]), "+f"(c[1]), "+f"(c[2]), "+f"(c[3])
        : "r"(a[0]), "r"(a[1]), "r"(a[2]), "r"(a[3]), "r"(b[0]), "r"(b[1]));
}

// A fragment: 16x16 bf16 from smem tile with 128B rows, chunk swizzle c^(row&7)
__device__ __forceinline__ void ldmA(uint32_t* f, uint32_t tile, int row0, int chunk0, int lane) {
    int row = row0 + (lane & 15);
    int c   = chunk0 + (lane >> 4);
    uint32_t addr = tile + row * 128 + ((c ^ (row & 7)) << 4);
    asm volatile("ldmatrix.sync.aligned.m8n8.x4.shared.b16 {%0,%1,%2,%3}, [%4];"
        : "=r"(f[0]), "=r"(f[1]), "=r"(f[2]), "=r"(f[3]) : "r"(addr));
}

// B fragment: 8(n)x16(k) from K-major [n][k] tile
__device__ __forceinline__ void ldmB(uint32_t* f, uint32_t tile, int row0, int chunk0, int lane) {
    int row = row0 + (lane & 7);
    int c   = chunk0 + ((lane >> 3) & 1);
    uint32_t addr = tile + row * 128 + ((c ^ (row & 7)) << 4);
    asm volatile("ldmatrix.sync.aligned.m8n8.x2.shared.b16 {%0,%1}, [%2];"
        : "=r"(f[0]), "=r"(f[1]) : "r"(addr));
}

__device__ __forceinline__ float ex2f_fast(float x) {
    float y;
    asm("ex2.approx.f32 %0, %1;" : "=f"(y) : "f"(x));
    return y;
}

__device__ __forceinline__ uint32_t pack_bf16(float a, float b) {
    __nv_bfloat162 t = __float22bfloat162_rn(make_float2(a, b));
    return *reinterpret_cast<uint32_t*>(&t);
}

// ---------------------------------------------------------------------------
// Conversion kernels: fp32 -> bf16 hi/lo split (a = hi + lo, ~16 mantissa bits)
// ---------------------------------------------------------------------------
__global__ void conv_hilo_kernel(const float* __restrict__ in,
                                 __nv_bfloat16* __restrict__ hi,
                                 __nv_bfloat16* __restrict__ lo, int n4)
{
    int i = blockIdx.x * blockDim.x + threadIdx.x;
    if (i >= n4) return;
    float4 v = reinterpret_cast<const float4*>(in)[i];
    __nv_bfloat16 h0 = __float2bfloat16(v.x);
    __nv_bfloat16 h1 = __float2bfloat16(v.y);
    __nv_bfloat16 h2 = __float2bfloat16(v.z);
    __nv_bfloat16 h3 = __float2bfloat16(v.w);
    __nv_bfloat16 l0 = __float2bfloat16(v.x - __bfloat162float(h0));
    __nv_bfloat16 l1 = __float2bfloat16(v.y - __bfloat162float(h1));
    __nv_bfloat16 l2 = __float2bfloat16(v.z - __bfloat162float(h2));
    __nv_bfloat16 l3 = __float2bfloat16(v.w - __bfloat162float(h3));
    __nv_bfloat162* hp = reinterpret_cast<__nv_bfloat162*>(hi);
    __nv_bfloat162* lp = reinterpret_cast<__nv_bfloat162*>(lo);
    hp[2*i]   = __nv_bfloat162(h0, h1);
    hp[2*i+1] = __nv_bfloat162(h2, h3);
    lp[2*i]   = __nv_bfloat162(l0, l1);
    lp[2*i+1] = __nv_bfloat162(l2, l3);
}

// W[K][N] fp32 -> Wt_hi/Wt_lo [N][K] bf16 (transpose + split)
__global__ void wconv_kernel(const float* __restrict__ W,
                             __nv_bfloat16* __restrict__ th,
                             __nv_bfloat16* __restrict__ tl)
{
    __shared__ float t[32][33];
    int tx = threadIdx.x, ty = threadIdx.y;       // (32, 8)
    int n0 = blockIdx.x * 32, k0 = blockIdx.y * 32;
#pragma unroll
    for (int j = 0; j < 32; j += 8)
        t[ty + j][tx] = W[(long)(k0 + ty + j) * DM + n0 + tx];
    __syncthreads();
#pragma unroll
    for (int j = 0; j < 32; j += 8) {
        float x = t[tx][ty + j];
        long n = n0 + ty + j, k = k0 + tx;
        __nv_bfloat16 h = __float2bfloat16(x);
        th[n * DM + k] = h;
        tl[n * DM + k] = __float2bfloat16(x - __bfloat162float(h));
    }
}

// V [b,s,(h,d)] fp32 -> Vt [b,h,d,s] bf16 hi/lo (transpose + split)
__global__ void vtconv_kernel(const float* __restrict__ V,
                              __nv_bfloat16* __restrict__ th,
                              __nv_bfloat16* __restrict__ tl)
{
    __shared__ float t[32][33];
    int tx = threadIdx.x, ty = threadIdx.y;       // (32, 8)
    int s0 = blockIdx.x * 32, c0 = blockIdx.y * 32;
    int b  = blockIdx.z;
#pragma unroll
    for (int j = 0; j < 32; j += 8)
        t[ty + j][tx] = V[((long)b * SEQ + s0 + ty + j) * DM + c0 + tx];
    __syncthreads();
#pragma unroll
    for (int j = 0; j < 32; j += 8) {
        float x = t[tx][ty + j];                  // (s = s0+tx, c = c0+ty+j)
        int c = c0 + ty + j;
        int h = c >> 6, d = c & 63;
        long off = (((long)b * NH + h) * HD + d) * SEQ + s0 + tx;
        __nv_bfloat16 hh = __float2bfloat16(x);
        th[off] = hh;
        tl[off] = __float2bfloat16(x - __bfloat162float(hh));
    }
}

// ---------------------------------------------------------------------------
// mma.sync bf16x3 GEMM: C[M,N] = (Ah+Al)[M,K] * ((Bh+Bl)[N,K])^T + bias
// ---------------------------------------------------------------------------
#define GBM 128
#define GBN 128
#define GBK 32
#define NCHUNK (DM / GBK)          // 32
#define TILEB  (128 * 128)         // 16KB per (A or B) buffer
#define GEMM_SMEM (4 * TILEB)      // 65536

__device__ __forceinline__ void stsw(char* tile, int row, int c, uint4 v) {
    uint32_t off = (uint32_t)(row * 128 + ((c ^ (row & 7)) << 4));
    *reinterpret_cast<uint4*>(tile + off) = v;
}

__global__ __launch_bounds__(256, 1) void gemm_tc_kernel(
    const __nv_bfloat16* __restrict__ Ah, const __nv_bfloat16* __restrict__ Al,
    const __nv_bfloat16* __restrict__ Bh, const __nv_bfloat16* __restrict__ Bl,
    const float* __restrict__ bias, float* __restrict__ C)
{
    extern __shared__ char gsm[];
    const uint32_t sbase = smem_to_u32(gsm);
    const int tid  = threadIdx.x;
    const int wid  = tid >> 5;
    const int lane = tid & 31;
    const int wm   = (wid >> 2) * 64;
    const int wn   = (wid & 3) * 32;
    const long bm  = (long)blockIdx.y * GBM;
    const int  bn  = blockIdx.x * GBN;

    const int urow = tid >> 2;
    const int uc   = tid & 3;

    float acc[4][4][4];
#pragma unroll
    for (int mi = 0; mi < 4; mi++)
#pragma unroll
        for (int ni = 0; ni < 4; ni++)
#pragma unroll
            for (int q = 0; q < 4; q++) acc[mi][ni][q] = 0.f;

    {
        char* bA = gsm;
        char* bB = gsm + TILEB;
#pragma unroll
        for (int t = 0; t < 2; t++) {
            int row = urow + t * 64;
            const long go = (bm + row) * DM + uc * 8;
            const long gn = ((long)bn + row) * DM + uc * 8;
            stsw(bA, row, uc,     *(const uint4*)(Ah + go));
            stsw(bA, row, uc + 4, *(const uint4*)(Al + go));
            stsw(bB, row, uc,     *(const uint4*)(Bh + gn));
            stsw(bB, row, uc + 4, *(const uint4*)(Bl + gn));
        }
    }
    __syncthreads();

    for (int it = 0; it < NCHUNK; ++it) {
        const int buf = it & 1;
        const uint32_t sA = sbase + buf * 2 * TILEB;
        const uint32_t sB = sA + TILEB;

        uint4 pAh[2], pAl[2], pBh[2], pBl[2];
        if (it + 1 < NCHUNK) {
            const int k0 = (it + 1) * GBK;
#pragma unroll
            for (int t = 0; t < 2; t++) {
                int row = urow + t * 64;
                const long go = (bm + row) * DM + k0 + uc * 8;
                const long gn = ((long)bn + row) * DM + k0 + uc * 8;
                pAh[t] = *(const uint4*)(Ah + go);
                pAl[t] = *(const uint4*)(Al + go);
                pBh[t] = *(const uint4*)(Bh + gn);
                pBl[t] = *(const uint4*)(Bl + gn);
            }
        }

#pragma unroll
        for (int ks = 0; ks < 2; ks++) {
            uint32_t afh[4][4], afl[4][4];
#pragma unroll
            for (int mi = 0; mi < 4; mi++) {
                ldmA(afh[mi], sA, wm + mi * 16, ks * 2,     lane);
                ldmA(afl[mi], sA, wm + mi * 16, ks * 2 + 4, lane);
            }
            uint32_t bfh[4][2], bfl[4][2];
#pragma unroll
            for (int ni = 0; ni < 4; ni++) {
                ldmB(bfh[ni], sB, wn + ni * 8, ks * 2,     lane);
                ldmB(bfl[ni], sB, wn + ni * 8, ks * 2 + 4, lane);
            }
#pragma unroll
            for (int mi = 0; mi < 4; mi++)
#pragma unroll
                for (int ni = 0; ni < 4; ni++) {
                    mma16816(acc[mi][ni], afh[mi], bfh[ni]);
                    mma16816(acc[mi][ni], afh[mi], bfl[ni]);
                    mma16816(acc[mi][ni], afl[mi], bfh[ni]);
                }
        }

        __syncthreads();

        if (it + 1 < NCHUNK) {
            char* bA = gsm + ((it + 1) & 1) * 2 * TILEB;
            char* bB = bA + TILEB;
#pragma unroll
            for (int t = 0; t < 2; t++) {
                int row = urow + t * 64;
                stsw(bA, row, uc,     pAh[t]);
                stsw(bA, row, uc + 4, pAl[t]);
                stsw(bB, row, uc,     pBh[t]);
                stsw(bB, row, uc + 4, pBl[t]);
            }
        }
        __syncthreads();
    }

#pragma unroll
    for (int mi = 0; mi < 4; mi++) {
#pragma unroll
        for (int ni = 0; ni < 4; ni++) {
            long r0  = bm + wm + mi * 16 + (lane >> 2);
            int  col = bn + wn + ni * 8 + (lane & 3) * 2;
            float2 bv = *(const float2*)&bias[col];
            float2 v0, v1;
            v0.x = acc[mi][ni][0] + bv.x; v0.y = acc[mi][ni][1] + bv.y;
            v1.x = acc[mi][ni][2] + bv.x; v1.y = acc[mi][ni][3] + bv.y;
            *(float2*)&C[r0 * DM + col]       = v0;
            *(float2*)&C[(r0 + 8) * DM + col] = v1;
        }
    }
}

// ---------------------------------------------------------------------------
// mma.sync flash attention. grid=(SEQ/128, B*NH), 128 threads (4 warps).
// Q tile 128 rows (resident), K/V tiles 64. bf16 hi/lo 3-term on both GEMMs.
// ---------------------------------------------------------------------------
#define SQH 0
#define SQL 16384
#define SKH 32768
#define SKL 40960
#define SVH 49152
#define SVL 57344
#define ATTN_SMEM 65536
#define SFC 0.18033688011112042f   // 0.125 * log2(e)

__global__ __launch_bounds__(128, 2) void attn_tc_kernel(
    const __nv_bfloat16* __restrict__ Qh, const __nv_bfloat16* __restrict__ Ql,
    const __nv_bfloat16* __restrict__ Kh, const __nv_bfloat16* __restrict__ Kl,
    const __nv_bfloat16* __restrict__ Vth, const __nv_bfloat16* __restrict__ Vtl,
    float* __restrict__ Og)
{
    extern __shared__ char smc[];
    const uint32_t sb = smem_to_u32(smc);
    const int tid  = threadIdx.x;
    const int wid  = tid >> 5;
    const int lane = tid & 31;
    const int bh   = blockIdx.y;
    const int b    = bh >> 4;
    const int h    = bh & 15;
    const int q0   = blockIdx.x * 128;
    const int hcol = h * HD;

    const long qrow0 = (long)b * SEQ + q0;
    const long krow0 = (long)b * SEQ;
    const long vbase = (long)bh * HD * SEQ;

    // Load Q tile (128 rows x 64 bf16 = 8 chunks/row), hi+lo
#pragma unroll
    for (int i = 0; i < 8; i++) {
        int idx = i * 128 + tid;
        int r = idx >> 3, c = idx & 7;
        long off = (qrow0 + r) * DM + hcol + c * 8;
        stsw(smc + SQH, r, c, *(const uint4*)(Qh + off));
        stsw(smc + SQL, r, c, *(const uint4*)(Ql + off));
    }

    float o[2][8][4];
    float mrow[2][2], lrow[2][2];
#pragma unroll
    for (int mi = 0; mi < 2; mi++) {
#pragma unroll
        for (int hf = 0; hf < 2; hf++) { mrow[mi][hf] = -INFINITY; lrow[mi][hf] = 0.f; }
#pragma unroll
        for (int ni = 0; ni < 8; ni++)
#pragma unroll
            for (int q = 0; q < 4; q++) o[mi][ni][q] = 0.f;
    }

    const int wm = wid * 32;

    for (int kt = 0; kt < SEQ / 64; ++kt) {
        __syncthreads();   // prior reads of K/V smem done (first iter: Q visible too)
        {
            const long kr = krow0 + kt * 64;
#pragma unroll
            for (int i = 0; i < 4; i++) {
                int idx = i * 128 + tid;
                int r = idx >> 3, c = idx & 7;
                long ko = (kr + r) * DM + hcol + c * 8;
                long vo = vbase + (long)r * SEQ + kt * 64 + c * 8;
                stsw(smc + SKH, r, c, *(const uint4*)(Kh + ko));
                stsw(smc + SKL, r, c, *(const uint4*)(Kl + ko));
                stsw(smc + SVH, r, c, *(const uint4*)(Vth + vo));
                stsw(smc + SVL, r, c, *(const uint4*)(Vtl + vo));
            }
        }
        __syncthreads();

        // ---- S = Q K^T (3-term split) ----
        float s[2][8][4];
#pragma unroll
        for (int mi = 0; mi < 2; mi++)
#pragma unroll
            for (int ni = 0; ni < 8; ni++)
#pragma unroll
                for (int q = 0; q < 4; q++) s[mi][ni][q] = 0.f;

#pragma unroll
        for (int ks = 0; ks < 4; ks++) {
            uint32_t aH[2][4], aL[2][4];
#pragma unroll
            for (int mi = 0; mi < 2; mi++) {
                ldmA(aH[mi], sb + SQH, wm + mi * 16, ks * 2, lane);
                ldmA(aL[mi], sb + SQL, wm + mi * 16, ks * 2, lane);
            }
#pragma unroll
            for (int ni = 0; ni < 8; ni++) {
                uint32_t bh2[2], bl2[2];
                ldmB(bh2, sb + SKH, ni * 8, ks * 2, lane);
                ldmB(bl2, sb + SKL, ni * 8, ks * 2, lane);
#pragma unroll
                for (int mi = 0; mi < 2; mi++) {
                    mma16816(s[mi][ni], aH[mi], bh2);
                    mma16816(s[mi][ni], aH[mi], bl2);
                    mma16816(s[mi][ni], aL[mi], bh2);
                }
            }
        }

        // ---- online softmax ----
#pragma unroll
        for (int mi = 0; mi < 2; mi++) {
#pragma unroll
            for (int hf = 0; hf < 2; hf++) {
                float mx = -INFINITY;
#pragma unroll
                for (int ni = 0; ni < 8; ni++) {
                    mx = fmaxf(mx, s[mi][ni][hf * 2]);
                    mx = fmaxf(mx, s[mi][ni][hf * 2 + 1]);
                }
                mx = fmaxf(mx, __shfl_xor_sync(0xffffffffu, mx, 1));
                mx = fmaxf(mx, __shfl_xor_sync(0xffffffffu, mx, 2));
                float mnew = fmaxf(mrow[mi][hf], mx);
                float corr = ex2f_fast((mrow[mi][hf] - mnew) * SFC);
                mrow[mi][hf] = mnew;
                float nmc = -mnew * SFC;
                float rs = 0.f;
#pragma unroll
                for (int ni = 0; ni < 8; ni++) {
                    float p0 = ex2f_fast(fmaf(s[mi][ni][hf * 2],     SFC, nmc));
                    float p1 = ex2f_fast(fmaf(s[mi][ni][hf * 2 + 1], SFC, nmc));
                    s[mi][ni][hf * 2]     = p0;
                    s[mi][ni][hf * 2 + 1] = p1;
                    rs += p0 + p1;
                }
                rs += __shfl_xor_sync(0xffffffffu, rs, 1);
                rs += __shfl_xor_sync(0xffffffffu, rs, 2);
                lrow[mi][hf] = lrow[mi][hf] * corr + rs;
#pragma unroll
                for (int ni = 0; ni < 8; ni++) {
                    o[mi][ni][hf * 2]     *= corr;
                    o[mi][ni][hf * 2 + 1] *= corr;
                }
            }
        }

        // ---- O += P V (P split to bf16 hi/lo in registers) ----
#pragma unroll
        for (int ks = 0; ks < 4; ks++) {
            uint32_t aPh[2][4], aPl[2][4];
#pragma unroll
            for (int mi = 0; mi < 2; mi++) {
                const float* t0 = s[mi][2 * ks];
                const float* t1 = s[mi][2 * ks + 1];
                float vs[8] = {t0[0], t0[1], t0[2], t0[3], t1[0], t1[1], t1[2], t1[3]};
#pragma unroll
                for (int p = 0; p < 4; p++) {
                    uint32_t hb = pack_bf16(vs[2 * p], vs[2 * p + 1]);
                    aPh[mi][p] = hb;
                    float2 bk = __bfloat1622float2(*reinterpret_cast<__nv_bfloat162*>(&hb));
                    aPl[mi][p] = pack_bf16(vs[2 * p] - bk.x, vs[2 * p + 1] - bk.y);
                }
            }
#pragma unroll
            for (int ni = 0; ni < 8; ni++) {
                uint32_t bvh[2], bvl[2];
                ldmB(bvh, sb + SVH, ni * 8, ks * 2, lane);
                ldmB(bvl, sb + SVL, ni * 8, ks * 2, lane);
#pragma unroll
                for (int mi = 0; mi < 2; mi++) {
                    mma16816(o[mi][ni], aPh[mi], bvh);
                    mma16816(o[mi][ni], aPh[mi], bvl);
                    mma16816(o[mi][ni], aPl[mi], bvh);
                }
            }
        }
    }

    // ---- epilogue: O / l -> Og ----
#pragma unroll
    for (int mi = 0; mi < 2; mi++) {
#pragma unroll
        for (int hf = 0; hf < 2; hf++) {
            float inv = 1.f / lrow[mi][hf];
            long row = qrow0 + wm + mi * 16 + hf * 8 + (lane >> 2);
#pragma unroll
            for (int ni = 0; ni < 8; ni++) {
                int col = hcol + ni * 8 + (lane & 3) * 2;
                float2 v;
                v.x = o[mi][ni][hf * 2]     * inv;
                v.y = o[mi][ni][hf * 2 + 1] * inv;
                *(float2*)&Og[row * DM + col] = v;
            }
        }
    }
}

// ---------------------------------------------------------------------------
extern "C" void kernel_launch(void* const* d_in, const int* in_sizes, int n_in,
                              void* d_out, int out_size)
{
    const float* query = (const float*)d_in[0];
    const float* key_  = (const float*)d_in[1];
    const float* value = (const float*)d_in[2];
    const float* Wq    = (const float*)d_in[3];
    const float* bq    = (const float*)d_in[4];
    const float* Wk    = (const float*)d_in[5];
    const float* bk    = (const float*)d_in[6];
    const float* Wv    = (const float*)d_in[7];
    const float* bv    = (const float*)d_in[8];
    const float* Wo    = (const float*)d_in[9];
    const float* bo    = (const float*)d_in[10];

    float *qp, *kp, *vp, *ctx;
    __nv_bfloat16 *ah, *al, *wh, *wl, *qh, *ql, *kh, *kl, *vth, *vtl;
    cudaGetSymbolAddress((void**)&qp,  g_Qp);
    cudaGetSymbolAddress((void**)&kp,  g_Kp);
    cudaGetSymbolAddress((void**)&vp,  g_Vp);
    cudaGetSymbolAddress((void**)&ctx, g_ctx);
    cudaGetSymbolAddress((void**)&ah,  g_Ah);
    cudaGetSymbolAddress((void**)&al,  g_Al);
    cudaGetSymbolAddress((void**)&wh,  g_Wh);
    cudaGetSymbolAddress((void**)&wl,  g_Wl);
    cudaGetSymbolAddress((void**)&qh,  g_Qh);
    cudaGetSymbolAddress((void**)&ql,  g_Ql);
    cudaGetSymbolAddress((void**)&kh,  g_Kh);
    cudaGetSymbolAddress((void**)&kl,  g_Kl);
    cudaGetSymbolAddress((void**)&vth, g_Vth);
    cudaGetSymbolAddress((void**)&vtl, g_Vtl);

    cudaFuncSetAttribute(gemm_tc_kernel,
                         cudaFuncAttributeMaxDynamicSharedMemorySize, GEMM_SMEM);
    cudaFuncSetAttribute(attn_tc_kernel,
                         cudaFuncAttributeMaxDynamicSharedMemorySize, ATTN_SMEM);

    const int n4 = MTOT * DM / 4;
    dim3 wgrid(DM / 32, DM / 32);
    dim3 wblk(32, 8);
    dim3 ggrid(DM / GBN, MTOT / GBM);

    // Q projection
    wconv_kernel<<<wgrid, wblk>>>(Wq, wh, wl);
    conv_hilo_kernel<<<n4 / 256, 256>>>(query, ah, al, n4);
    gemm_tc_kernel<<<ggrid, 256, GEMM_SMEM>>>(ah, al, wh, wl, bq, qp);
    // K projection
    wconv_kernel<<<wgrid, wblk>>>(Wk, wh, wl);
    conv_hilo_kernel<<<n4 / 256, 256>>>(key_, ah, al, n4);
    gemm_tc_kernel<<<ggrid, 256, GEMM_SMEM>>>(ah, al, wh, wl, bk, kp);
    // V projection
    wconv_kernel<<<wgrid, wblk>>>(Wv, wh, wl);
    conv_hilo_kernel<<<n4 / 256, 256>>>(value, ah, al, n4);
    gemm_tc_kernel<<<ggrid, 256, GEMM_SMEM>>>(ah, al, wh, wl, bv, vp);

    // Attention operand prep (bf16 hi/lo; V transposed per head)
    conv_hilo_kernel<<<n4 / 256, 256>>>(qp, qh, ql, n4);
    conv_hilo_kernel<<<n4 / 256, 256>>>(kp, kh, kl, n4);
    dim3 vgrid(SEQ / 32, DM / 32, BATCH);
    vtconv_kernel<<<vgrid, wblk>>>(vp, vth, vtl);

    // Attention
    dim3 agrid(SEQ / 128, BATCH * NH);
    attn_tc_kernel<<<agrid, 128, ATTN_SMEM>>>(qh, ql, kh, kl, vth, vtl, ctx);

    // Output projection
    wconv_kernel<<<wgrid, wblk>>>(Wo, wh, wl);
    conv_hilo_kernel<<<n4 / 256, 256>>>(ctx, ah, al, n4);
    gemm_tc_kernel<<<ggrid, 256, GEMM_SMEM>>>(ah, al, wh, wl, bo, (float*)d_out);
}

// round 7
// speedup vs baseline: 3.7117x; 1.1632x over previous
#include <cuda_runtime.h>
#include <cuda_bf16.h>
#include <cstdint>
#include <math.h>

#define SEQ    2048
#define DM     1024
#define NH     16
#define HD     64
#define BATCH  2
#define MTOT   (BATCH*SEQ)   // 4096

// ---------------------------------------------------------------------------
// Scratch (__device__ globals; allocation-free rule)
// ---------------------------------------------------------------------------
__device__ float g_Vp[MTOT*DM];
__device__ float g_ctx[MTOT*DM];
__device__ __nv_bfloat16 g_Ah[MTOT*DM];
__device__ __nv_bfloat16 g_Al[MTOT*DM];
__device__ __nv_bfloat16 g_Wh[DM*DM];
__device__ __nv_bfloat16 g_Wl[DM*DM];
__device__ __nv_bfloat16 g_Qh[MTOT*DM];
__device__ __nv_bfloat16 g_Ql[MTOT*DM];
__device__ __nv_bfloat16 g_Kh[MTOT*DM];
__device__ __nv_bfloat16 g_Kl[MTOT*DM];
__device__ __nv_bfloat16 g_Vth[MTOT*DM];   // [b][h][d][s]
__device__ __nv_bfloat16 g_Vtl[MTOT*DM];

// ---------------------------------------------------------------------------
// PTX helpers (baseline PTX — works on compute_103 target)
// ---------------------------------------------------------------------------
__device__ __forceinline__ uint32_t smem_to_u32(const void* smem_ptr) {
    uint32_t addr;
    asm("{ .reg .u64 tmp; cvta.to.shared.u64 tmp, %1; cvt.u32.u64 %0, tmp; }"
        : "=r"(addr) : "l"(smem_ptr));
    return addr;
}

__device__ __forceinline__ void mma16816(float* c, const uint32_t* a, const uint32_t* b) {
    asm volatile(
        "mma.sync.aligned.m16n8k16.row.col.f32.bf16.bf16.f32 "
        "{%0,%1,%2,%3}, {%4,%5,%6,%7}, {%8,%9}, {%0,%1,%2,%3};"
        : "+f"(c[0]), "+f"(c[1]), "+f"(c[2]), "+f"(c[3])
        : "r"(a[0]), "r"(a[1]), "r"(a[2]), "r"(a[3]), "r"(b[0]), "r"(b[1]));
}

// A fragment: 16x16 bf16 from smem tile with 128B rows, chunk swizzle c^(row&7)
__device__ __forceinline__ void ldmA(uint32_t* f, uint32_t tile, int row0, int chunk0, int lane) {
    int row = row0 + (lane & 15);
    int c   = chunk0 + (lane >> 4);
    uint32_t addr = tile + row * 128 + ((c ^ (row & 7)) << 4);
    asm volatile("ldmatrix.sync.aligned.m8n8.x4.shared.b16 {%0,%1,%2,%3}, [%4];"
        : "=r"(f[0]), "=r"(f[1]), "=r"(f[2]), "=r"(f[3]) : "r"(addr));
}

// B fragment: 8(n)x16(k) from K-major [n][k] tile
__device__ __forceinline__ void ldmB(uint32_t* f, uint32_t tile, int row0, int chunk0, int lane) {
    int row = row0 + (lane & 7);
    int c   = chunk0 + ((lane >> 3) & 1);
    uint32_t addr = tile + row * 128 + ((c ^ (row & 7)) << 4);
    asm volatile("ldmatrix.sync.aligned.m8n8.x2.shared.b16 {%0,%1}, [%2];"
        : "=r"(f[0]), "=r"(f[1]) : "r"(addr));
}

__device__ __forceinline__ float ex2f_fast(float x) {
    float y;
    asm("ex2.approx.f32 %0, %1;" : "=f"(y) : "f"(x));
    return y;
}

__device__ __forceinline__ uint32_t pack_bf16(float a, float b) {
    __nv_bfloat162 t = __float22bfloat162_rn(make_float2(a, b));
    return *reinterpret_cast<uint32_t*>(&t);
}

__device__ __forceinline__ void cp_async16(uint32_t smem_addr, const void* gptr) {
    asm volatile("cp.async.cg.shared.global [%0], [%1], 16;"
        :: "r"(smem_addr), "l"(gptr));
}
#define CP_COMMIT() asm volatile("cp.async.commit_group;" ::: "memory")
#define CP_WAIT1()  asm volatile("cp.async.wait_group 1;" ::: "memory")

// ---------------------------------------------------------------------------
// Conversion kernels
// ---------------------------------------------------------------------------
__global__ void conv_hilo_kernel(const float* __restrict__ in,
                                 __nv_bfloat16* __restrict__ hi,
                                 __nv_bfloat16* __restrict__ lo, int n4)
{
    int i = blockIdx.x * blockDim.x + threadIdx.x;
    if (i >= n4) return;
    float4 v = reinterpret_cast<const float4*>(in)[i];
    __nv_bfloat16 h0 = __float2bfloat16(v.x);
    __nv_bfloat16 h1 = __float2bfloat16(v.y);
    __nv_bfloat16 h2 = __float2bfloat16(v.z);
    __nv_bfloat16 h3 = __float2bfloat16(v.w);
    __nv_bfloat16 l0 = __float2bfloat16(v.x - __bfloat162float(h0));
    __nv_bfloat16 l1 = __float2bfloat16(v.y - __bfloat162float(h1));
    __nv_bfloat16 l2 = __float2bfloat16(v.z - __bfloat162float(h2));
    __nv_bfloat16 l3 = __float2bfloat16(v.w - __bfloat162float(h3));
    __nv_bfloat162* hp = reinterpret_cast<__nv_bfloat162*>(hi);
    __nv_bfloat162* lp = reinterpret_cast<__nv_bfloat162*>(lo);
    hp[2*i]   = __nv_bfloat162(h0, h1);
    hp[2*i+1] = __nv_bfloat162(h2, h3);
    lp[2*i]   = __nv_bfloat162(l0, l1);
    lp[2*i+1] = __nv_bfloat162(l2, l3);
}

// W[K][N] fp32 -> Wt_hi/Wt_lo [N][K] bf16 (transpose + split)
__global__ void wconv_kernel(const float* __restrict__ W,
                             __nv_bfloat16* __restrict__ th,
                             __nv_bfloat16* __restrict__ tl)
{
    __shared__ float t[32][33];
    int tx = threadIdx.x, ty = threadIdx.y;       // (32, 8)
    int n0 = blockIdx.x * 32, k0 = blockIdx.y * 32;
#pragma unroll
    for (int j = 0; j < 32; j += 8)
        t[ty + j][tx] = W[(long)(k0 + ty + j) * DM + n0 + tx];
    __syncthreads();
#pragma unroll
    for (int j = 0; j < 32; j += 8) {
        float x = t[tx][ty + j];
        long n = n0 + ty + j, k = k0 + tx;
        __nv_bfloat16 h = __float2bfloat16(x);
        th[n * DM + k] = h;
        tl[n * DM + k] = __float2bfloat16(x - __bfloat162float(h));
    }
}

// V [b,s,(h,d)] fp32 -> Vt [b,h,d,s] bf16 hi/lo (transpose + split)
__global__ void vtconv_kernel(const float* __restrict__ V,
                              __nv_bfloat16* __restrict__ th,
                              __nv_bfloat16* __restrict__ tl)
{
    __shared__ float t[32][33];
    int tx = threadIdx.x, ty = threadIdx.y;       // (32, 8)
    int s0 = blockIdx.x * 32, c0 = blockIdx.y * 32;
    int b  = blockIdx.z;
#pragma unroll
    for (int j = 0; j < 32; j += 8)
        t[ty + j][tx] = V[((long)b * SEQ + s0 + ty + j) * DM + c0 + tx];
    __syncthreads();
#pragma unroll
    for (int j = 0; j < 32; j += 8) {
        float x = t[tx][ty + j];                  // (s = s0+tx, c = c0+ty+j)
        int c = c0 + ty + j;
        int h = c >> 6, d = c & 63;
        long off = (((long)b * NH + h) * HD + d) * SEQ + s0 + tx;
        __nv_bfloat16 hh = __float2bfloat16(x);
        th[off] = hh;
        tl[off] = __float2bfloat16(x - __bfloat162float(hh));
    }
}

// ---------------------------------------------------------------------------
// mma.sync bf16x3 GEMM with cp.async 3-stage pipeline.
// C[M,N] = (Ah+Al)[M,K] * ((Bh+Bl)[N,K])^T + bias
// If C != null: fp32 out. Else: bf16 hi/lo out (Oh/Ol).
// ---------------------------------------------------------------------------
#define GBM 128
#define GBN 128
#define GBK 32
#define NCHUNK (DM / GBK)          // 32
#define HTILE  16384               // 16KB (A or B) per stage
#define STAGEB (2 * HTILE)         // 32KB per stage
#define GEMM_SMEM (3 * STAGEB)     // 98304

__device__ __forceinline__ void gemm_load_stage(
    uint32_t sA, uint32_t sB,
    const __nv_bfloat16* __restrict__ Ah, const __nv_bfloat16* __restrict__ Al,
    const __nv_bfloat16* __restrict__ Bh, const __nv_bfloat16* __restrict__ Bl,
    long bm, long bn, int k0, int urow, int uc)
{
#pragma unroll
    for (int t = 0; t < 2; t++) {
        int row = urow + t * 64;
        const long go = (bm + row) * DM + k0 + uc * 8;
        const long gn = (bn + row) * DM + k0 + uc * 8;
        uint32_t offH = (uint32_t)(row * 128 + ((uc       ^ (row & 7)) << 4));
        uint32_t offL = (uint32_t)(row * 128 + (((uc + 4) ^ (row & 7)) << 4));
        cp_async16(sA + offH, Ah + go);
        cp_async16(sA + offL, Al + go);
        cp_async16(sB + offH, Bh + gn);
        cp_async16(sB + offL, Bl + gn);
    }
}

__global__ __launch_bounds__(256, 2) void gemm_tc_kernel(
    const __nv_bfloat16* __restrict__ Ah, const __nv_bfloat16* __restrict__ Al,
    const __nv_bfloat16* __restrict__ Bh, const __nv_bfloat16* __restrict__ Bl,
    const float* __restrict__ bias, float* __restrict__ C,
    __nv_bfloat16* __restrict__ Oh, __nv_bfloat16* __restrict__ Ol)
{
    extern __shared__ char gsm[];
    const uint32_t sbase = smem_to_u32(gsm);
    const int tid  = threadIdx.x;
    const int wid  = tid >> 5;
    const int lane = tid & 31;
    const int wm   = (wid >> 2) * 64;
    const int wn   = (wid & 3) * 32;
    const long bm  = (long)blockIdx.y * GBM;
    const long bn  = (long)blockIdx.x * GBN;

    const int urow = tid >> 2;
    const int uc   = tid & 3;

    float acc[4][4][4];
#pragma unroll
    for (int mi = 0; mi < 4; mi++)
#pragma unroll
        for (int ni = 0; ni < 4; ni++)
#pragma unroll
            for (int q = 0; q < 4; q++) acc[mi][ni][q] = 0.f;

    // Prologue: stages 0 and 1 in flight
    gemm_load_stage(sbase, sbase + HTILE, Ah, Al, Bh, Bl, bm, bn, 0, urow, uc);
    CP_COMMIT();
    gemm_load_stage(sbase + STAGEB, sbase + STAGEB + HTILE, Ah, Al, Bh, Bl, bm, bn, GBK, urow, uc);
    CP_COMMIT();

    for (int it = 0; it < NCHUNK; ++it) {
        CP_WAIT1();          // group #it complete (<=1 outstanding)
        __syncthreads();     // visible to all warps; prior compute on stage (it+2)%3 done

        const int nx = it + 2;
        if (nx < NCHUNK) {
            const uint32_t st = sbase + (nx % 3) * STAGEB;
            gemm_load_stage(st, st + HTILE, Ah, Al, Bh, Bl, bm, bn, nx * GBK, urow, uc);
        }
        CP_COMMIT();         // commit (possibly empty) to keep group numbering

        const uint32_t sA = sbase + (it % 3) * STAGEB;
        const uint32_t sB = sA + HTILE;

#pragma unroll
        for (int ks = 0; ks < 2; ks++) {
            uint32_t afh[4][4], afl[4][4];
#pragma unroll
            for (int mi = 0; mi < 4; mi++) {
                ldmA(afh[mi], sA, wm + mi * 16, ks * 2,     lane);
                ldmA(afl[mi], sA, wm + mi * 16, ks * 2 + 4, lane);
            }
            uint32_t bfh[4][2], bfl[4][2];
#pragma unroll
            for (int ni = 0; ni < 4; ni++) {
                ldmB(bfh[ni], sB, wn + ni * 8, ks * 2,     lane);
                ldmB(bfl[ni], sB, wn + ni * 8, ks * 2 + 4, lane);
            }
#pragma unroll
            for (int mi = 0; mi < 4; mi++)
#pragma unroll
                for (int ni = 0; ni < 4; ni++) {
                    mma16816(acc[mi][ni], afh[mi], bfh[ni]);
                    mma16816(acc[mi][ni], afh[mi], bfl[ni]);
                    mma16816(acc[mi][ni], afl[mi], bfh[ni]);
                }
        }
    }

    // Epilogue
#pragma unroll
    for (int mi = 0; mi < 4; mi++) {
#pragma unroll
        for (int ni = 0; ni < 4; ni++) {
            long r0  = bm + wm + mi * 16 + (lane >> 2);
            long col = bn + wn + ni * 8 + (lane & 3) * 2;
            float2 bv = *(const float2*)&bias[col];
            float2 v0, v1;
            v0.x = acc[mi][ni][0] + bv.x; v0.y = acc[mi][ni][1] + bv.y;
            v1.x = acc[mi][ni][2] + bv.x; v1.y = acc[mi][ni][3] + bv.y;
            if (C) {
                *(float2*)&C[r0 * DM + col]       = v0;
                *(float2*)&C[(r0 + 8) * DM + col] = v1;
            } else {
                uint32_t h0 = pack_bf16(v0.x, v0.y);
                uint32_t h1 = pack_bf16(v1.x, v1.y);
                float2 f0 = __bfloat1622float2(*reinterpret_cast<__nv_bfloat162*>(&h0));
                float2 f1 = __bfloat1622float2(*reinterpret_cast<__nv_bfloat162*>(&h1));
                uint32_t l0 = pack_bf16(v0.x - f0.x, v0.y - f0.y);
                uint32_t l1 = pack_bf16(v1.x - f1.x, v1.y - f1.y);
                *(uint32_t*)&Oh[r0 * DM + col]       = h0;
                *(uint32_t*)&Oh[(r0 + 8) * DM + col] = h1;
                *(uint32_t*)&Ol[r0 * DM + col]       = l0;
                *(uint32_t*)&Ol[(r0 + 8) * DM + col] = l1;
            }
        }
    }
}

// ---------------------------------------------------------------------------
// mma.sync flash attention. grid=(SEQ/128, B*NH), 128 threads (4 warps).
// Q tile 128 rows (resident), K/V tiles 64. bf16 hi/lo 3-term on both GEMMs.
// ---------------------------------------------------------------------------
#define SQH 0
#define SQL 16384
#define SKH 32768
#define SKL 40960
#define SVH 49152
#define SVL 57344
#define ATTN_SMEM 65536
#define SFC 0.18033688011112042f   // 0.125 * log2(e)

__device__ __forceinline__ void stsw(char* tile, int row, int c, uint4 v) {
    uint32_t off = (uint32_t)(row * 128 + ((c ^ (row & 7)) << 4));
    *reinterpret_cast<uint4*>(tile + off) = v;
}

__global__ __launch_bounds__(128, 2) void attn_tc_kernel(
    const __nv_bfloat16* __restrict__ Qh, const __nv_bfloat16* __restrict__ Ql,
    const __nv_bfloat16* __restrict__ Kh, const __nv_bfloat16* __restrict__ Kl,
    const __nv_bfloat16* __restrict__ Vth, const __nv_bfloat16* __restrict__ Vtl,
    float* __restrict__ Og)
{
    extern __shared__ char smc[];
    const uint32_t sb = smem_to_u32(smc);
    const int tid  = threadIdx.x;
    const int wid  = tid >> 5;
    const int lane = tid & 31;
    const int bh   = blockIdx.y;
    const int b    = bh >> 4;
    const int h    = bh & 15;
    const int q0   = blockIdx.x * 128;
    const int hcol = h * HD;

    const long qrow0 = (long)b * SEQ + q0;
    const long krow0 = (long)b * SEQ;
    const long vbase = (long)bh * HD * SEQ;

    // Load Q tile (128 rows x 64 bf16 = 8 chunks/row), hi+lo
#pragma unroll
    for (int i = 0; i < 8; i++) {
        int idx = i * 128 + tid;
        int r = idx >> 3, c = idx & 7;
        long off = (qrow0 + r) * DM + hcol + c * 8;
        stsw(smc + SQH, r, c, *(const uint4*)(Qh + off));
        stsw(smc + SQL, r, c, *(const uint4*)(Ql + off));
    }

    float o[2][8][4];
    float mrow[2][2], lrow[2][2];
#pragma unroll
    for (int mi = 0; mi < 2; mi++) {
#pragma unroll
        for (int hf = 0; hf < 2; hf++) { mrow[mi][hf] = -INFINITY; lrow[mi][hf] = 0.f; }
#pragma unroll
        for (int ni = 0; ni < 8; ni++)
#pragma unroll
            for (int q = 0; q < 4; q++) o[mi][ni][q] = 0.f;
    }

    const int wm = wid * 32;

    for (int kt = 0; kt < SEQ / 64; ++kt) {
        __syncthreads();
        {
            const long kr = krow0 + kt * 64;
#pragma unroll
            for (int i = 0; i < 4; i++) {
                int idx = i * 128 + tid;
                int r = idx >> 3, c = idx & 7;
                long ko = (kr + r) * DM + hcol + c * 8;
                long vo = vbase + (long)r * SEQ + kt * 64 + c * 8;
                stsw(smc + SKH, r, c, *(const uint4*)(Kh + ko));
                stsw(smc + SKL, r, c, *(const uint4*)(Kl + ko));
                stsw(smc + SVH, r, c, *(const uint4*)(Vth + vo));
                stsw(smc + SVL, r, c, *(const uint4*)(Vtl + vo));
            }
        }
        __syncthreads();

        // ---- S = Q K^T (3-term split) ----
        float s[2][8][4];
#pragma unroll
        for (int mi = 0; mi < 2; mi++)
#pragma unroll
            for (int ni = 0; ni < 8; ni++)
#pragma unroll
                for (int q = 0; q < 4; q++) s[mi][ni][q] = 0.f;

#pragma unroll
        for (int ks = 0; ks < 4; ks++) {
            uint32_t aH[2][4], aL[2][4];
#pragma unroll
            for (int mi = 0; mi < 2; mi++) {
                ldmA(aH[mi], sb + SQH, wm + mi * 16, ks * 2, lane);
                ldmA(aL[mi], sb + SQL, wm + mi * 16, ks * 2, lane);
            }
#pragma unroll
            for (int ni = 0; ni < 8; ni++) {
                uint32_t bh2[2], bl2[2];
                ldmB(bh2, sb + SKH, ni * 8, ks * 2, lane);
                ldmB(bl2, sb + SKL, ni * 8, ks * 2, lane);
#pragma unroll
                for (int mi = 0; mi < 2; mi++) {
                    mma16816(s[mi][ni], aH[mi], bh2);
                    mma16816(s[mi][ni], aH[mi], bl2);
                    mma16816(s[mi][ni], aL[mi], bh2);
                }
            }
        }

        // ---- online softmax ----
#pragma unroll
        for (int mi = 0; mi < 2; mi++) {
#pragma unroll
            for (int hf = 0; hf < 2; hf++) {
                float mx = -INFINITY;
#pragma unroll
                for (int ni = 0; ni < 8; ni++) {
                    mx = fmaxf(mx, s[mi][ni][hf * 2]);
                    mx = fmaxf(mx, s[mi][ni][hf * 2 + 1]);
                }
                mx = fmaxf(mx, __shfl_xor_sync(0xffffffffu, mx, 1));
                mx = fmaxf(mx, __shfl_xor_sync(0xffffffffu, mx, 2));
                float mnew = fmaxf(mrow[mi][hf], mx);
                float corr = ex2f_fast((mrow[mi][hf] - mnew) * SFC);
                mrow[mi][hf] = mnew;
                float nmc = -mnew * SFC;
                float rs = 0.f;
#pragma unroll
                for (int ni = 0; ni < 8; ni++) {
                    float p0 = ex2f_fast(fmaf(s[mi][ni][hf * 2],     SFC, nmc));
                    float p1 = ex2f_fast(fmaf(s[mi][ni][hf * 2 + 1], SFC, nmc));
                    s[mi][ni][hf * 2]     = p0;
                    s[mi][ni][hf * 2 + 1] = p1;
                    rs += p0 + p1;
                }
                rs += __shfl_xor_sync(0xffffffffu, rs, 1);
                rs += __shfl_xor_sync(0xffffffffu, rs, 2);
                lrow[mi][hf] = lrow[mi][hf] * corr + rs;
#pragma unroll
                for (int ni = 0; ni < 8; ni++) {
                    o[mi][ni][hf * 2]     *= corr;
                    o[mi][ni][hf * 2 + 1] *= corr;
                }
            }
        }

        // ---- O += P V (P split to bf16 hi/lo in registers) ----
#pragma unroll
        for (int ks = 0; ks < 4; ks++) {
            uint32_t aPh[2][4], aPl[2][4];
#pragma unroll
            for (int mi = 0; mi < 2; mi++) {
                const float* t0 = s[mi][2 * ks];
                const float* t1 = s[mi][2 * ks + 1];
                float vs[8] = {t0[0], t0[1], t0[2], t0[3], t1[0], t1[1], t1[2], t1[3]};
#pragma unroll
                for (int p = 0; p < 4; p++) {
                    uint32_t hb = pack_bf16(vs[2 * p], vs[2 * p + 1]);
                    aPh[mi][p] = hb;
                    float2 bk = __bfloat1622float2(*reinterpret_cast<__nv_bfloat162*>(&hb));
                    aPl[mi][p] = pack_bf16(vs[2 * p] - bk.x, vs[2 * p + 1] - bk.y);
                }
            }
#pragma unroll
            for (int ni = 0; ni < 8; ni++) {
                uint32_t bvh[2], bvl[2];
                ldmB(bvh, sb + SVH, ni * 8, ks * 2, lane);
                ldmB(bvl, sb + SVL, ni * 8, ks * 2, lane);
#pragma unroll
                for (int mi = 0; mi < 2; mi++) {
                    mma16816(o[mi][ni], aPh[mi], bvh);
                    mma16816(o[mi][ni], aPh[mi], bvl);
                    mma16816(o[mi][ni], aPl[mi], bvh);
                }
            }
        }
    }

    // ---- epilogue: O / l -> Og ----
#pragma unroll
    for (int mi = 0; mi < 2; mi++) {
#pragma unroll
        for (int hf = 0; hf < 2; hf++) {
            float inv = 1.f / lrow[mi][hf];
            long row = qrow0 + wm + mi * 16 + hf * 8 + (lane >> 2);
#pragma unroll
            for (int ni = 0; ni < 8; ni++) {
                int col = hcol + ni * 8 + (lane & 3) * 2;
                float2 v;
                v.x = o[mi][ni][hf * 2]     * inv;
                v.y = o[mi][ni][hf * 2 + 1] * inv;
                *(float2*)&Og[row * DM + col] = v;
            }
        }
    }
}

// ---------------------------------------------------------------------------
extern "C" void kernel_launch(void* const* d_in, const int* in_sizes, int n_in,
                              void* d_out, int out_size)
{
    const float* query = (const float*)d_in[0];
    const float* key_  = (const float*)d_in[1];
    const float* value = (const float*)d_in[2];
    const float* Wq    = (const float*)d_in[3];
    const float* bq    = (const float*)d_in[4];
    const float* Wk    = (const float*)d_in[5];
    const float* bk    = (const float*)d_in[6];
    const float* Wv    = (const float*)d_in[7];
    const float* bv    = (const float*)d_in[8];
    const float* Wo    = (const float*)d_in[9];
    const float* bo    = (const float*)d_in[10];

    float *vp, *ctx;
    __nv_bfloat16 *ah, *al, *wh, *wl, *qh, *ql, *kh, *kl, *vth, *vtl;
    cudaGetSymbolAddress((void**)&vp,  g_Vp);
    cudaGetSymbolAddress((void**)&ctx, g_ctx);
    cudaGetSymbolAddress((void**)&ah,  g_Ah);
    cudaGetSymbolAddress((void**)&al,  g_Al);
    cudaGetSymbolAddress((void**)&wh,  g_Wh);
    cudaGetSymbolAddress((void**)&wl,  g_Wl);
    cudaGetSymbolAddress((void**)&qh,  g_Qh);
    cudaGetSymbolAddress((void**)&ql,  g_Ql);
    cudaGetSymbolAddress((void**)&kh,  g_Kh);
    cudaGetSymbolAddress((void**)&kl,  g_Kl);
    cudaGetSymbolAddress((void**)&vth, g_Vth);
    cudaGetSymbolAddress((void**)&vtl, g_Vtl);

    cudaFuncSetAttribute(gemm_tc_kernel,
                         cudaFuncAttributeMaxDynamicSharedMemorySize, GEMM_SMEM);
    cudaFuncSetAttribute(attn_tc_kernel,
                         cudaFuncAttributeMaxDynamicSharedMemorySize, ATTN_SMEM);

    const int n4 = MTOT * DM / 4;
    dim3 wgrid(DM / 32, DM / 32);
    dim3 wblk(32, 8);
    dim3 ggrid(DM / GBN, MTOT / GBM);

    // Q projection -> bf16 hi/lo directly
    wconv_kernel<<<wgrid, wblk>>>(Wq, wh, wl);
    conv_hilo_kernel<<<n4 / 256, 256>>>(query, ah, al, n4);
    gemm_tc_kernel<<<ggrid, 256, GEMM_SMEM>>>(ah, al, wh, wl, bq, nullptr, qh, ql);
    // K projection -> bf16 hi/lo directly
    wconv_kernel<<<wgrid, wblk>>>(Wk, wh, wl);
    conv_hilo_kernel<<<n4 / 256, 256>>>(key_, ah, al, n4);
    gemm_tc_kernel<<<ggrid, 256, GEMM_SMEM>>>(ah, al, wh, wl, bk, nullptr, kh, kl);
    // V projection -> fp32, then transpose/split
    wconv_kernel<<<wgrid, wblk>>>(Wv, wh, wl);
    conv_hilo_kernel<<<n4 / 256, 256>>>(value, ah, al, n4);
    gemm_tc_kernel<<<ggrid, 256, GEMM_SMEM>>>(ah, al, wh, wl, bv, vp, nullptr, nullptr);
    dim3 vgrid(SEQ / 32, DM / 32, BATCH);
    vtconv_kernel<<<vgrid, wblk>>>(vp, vth, vtl);

    // Attention
    dim3 agrid(SEQ / 128, BATCH * NH);
    attn_tc_kernel<<<agrid, 128, ATTN_SMEM>>>(qh, ql, kh, kl, vth, vtl, ctx);

    // Output projection -> fp32 out
    wconv_kernel<<<wgrid, wblk>>>(Wo, wh, wl);
    conv_hilo_kernel<<<n4 / 256, 256>>>(ctx, ah, al, n4);
    gemm_tc_kernel<<<ggrid, 256, GEMM_SMEM>>>(ah, al, wh, wl, bo, (float*)d_out, nullptr, nullptr);
}

// round 8
// speedup vs baseline: 3.9623x; 1.0675x over previous
#include <cuda_runtime.h>
#include <cuda_bf16.h>
#include <cstdint>
#include <math.h>

#define SEQ    2048
#define DM     1024
#define NH     16
#define HD     64
#define BATCH  2
#define MTOT   (BATCH*SEQ)   // 4096

// ---------------------------------------------------------------------------
// Scratch (__device__ globals; allocation-free rule)
// ---------------------------------------------------------------------------
__device__ __nv_bfloat16 g_Ah[MTOT*DM];
__device__ __nv_bfloat16 g_Al[MTOT*DM];
__device__ __nv_bfloat16 g_Wh[DM*DM];
__device__ __nv_bfloat16 g_Wl[DM*DM];
__device__ __nv_bfloat16 g_Qh[MTOT*DM];
__device__ __nv_bfloat16 g_Ql[MTOT*DM];
__device__ __nv_bfloat16 g_Kh[MTOT*DM];
__device__ __nv_bfloat16 g_Kl[MTOT*DM];
__device__ __nv_bfloat16 g_Vh[MTOT*DM];    // [b,s,dm] bf16 hi
__device__ __nv_bfloat16 g_Vl[MTOT*DM];    // [b,s,dm] bf16 lo

// ---------------------------------------------------------------------------
// PTX helpers (baseline PTX — works on compute_103 target)
// ---------------------------------------------------------------------------
__device__ __forceinline__ uint32_t smem_to_u32(const void* smem_ptr) {
    uint32_t addr;
    asm("{ .reg .u64 tmp; cvta.to.shared.u64 tmp, %1; cvt.u32.u64 %0, tmp; }"
        : "=r"(addr) : "l"(smem_ptr));
    return addr;
}

__device__ __forceinline__ void mma16816(float* c, const uint32_t* a, const uint32_t* b) {
    asm volatile(
        "mma.sync.aligned.m16n8k16.row.col.f32.bf16.bf16.f32 "
        "{%0,%1,%2,%3}, {%4,%5,%6,%7}, {%8,%9}, {%0,%1,%2,%3};"
        : "+f"(c[0]), "+f"(c[1]), "+f"(c[2]), "+f"(c[3])
        : "r"(a[0]), "r"(a[1]), "r"(a[2]), "r"(a[3]), "r"(b[0]), "r"(b[1]));
}

// A fragment: 16x16 bf16 from smem tile with 128B rows, chunk swizzle c^(row&7)
__device__ __forceinline__ void ldmA(uint32_t* f, uint32_t tile, int row0, int chunk0, int lane) {
    int row = row0 + (lane & 15);
    int c   = chunk0 + (lane >> 4);
    uint32_t addr = tile + row * 128 + ((c ^ (row & 7)) << 4);
    asm volatile("ldmatrix.sync.aligned.m8n8.x4.shared.b16 {%0,%1,%2,%3}, [%4];"
        : "=r"(f[0]), "=r"(f[1]), "=r"(f[2]), "=r"(f[3]) : "r"(addr));
}

// B fragment: 8(n)x16(k) from K-major [n][k] tile
__device__ __forceinline__ void ldmB(uint32_t* f, uint32_t tile, int row0, int chunk0, int lane) {
    int row = row0 + (lane & 7);
    int c   = chunk0 + ((lane >> 3) & 1);
    uint32_t addr = tile + row * 128 + ((c ^ (row & 7)) << 4);
    asm volatile("ldmatrix.sync.aligned.m8n8.x2.shared.b16 {%0,%1}, [%2];"
        : "=r"(f[0]), "=r"(f[1]) : "r"(addr));
}

// Transposed B fragment from an MN-major [k(s)][n(d)] tile: rows = k, 8 d per 16B.
// ldmatrix .trans turns memory (s,d) into fragment (n=d, k=s), exactly the
// col-major B operand for mma row.col.
__device__ __forceinline__ void ldmBt(uint32_t* f, uint32_t tile, int ni, int ks, int lane) {
    int row = ks * 16 + (lane & 7) + (((lane >> 3) & 1) << 3);
    uint32_t addr = tile + row * 128 + ((ni ^ (row & 7)) << 4);
    asm volatile("ldmatrix.sync.aligned.m8n8.x2.trans.shared.b16 {%0,%1}, [%2];"
        : "=r"(f[0]), "=r"(f[1]) : "r"(addr));
}

__device__ __forceinline__ float ex2f_fast(float x) {
    float y;
    asm("ex2.approx.f32 %0, %1;" : "=f"(y) : "f"(x));
    return y;
}

__device__ __forceinline__ uint32_t pack_bf16(float a, float b) {
    __nv_bfloat162 t = __float22bfloat162_rn(make_float2(a, b));
    return *reinterpret_cast<uint32_t*>(&t);
}

__device__ __forceinline__ void cp_async16(uint32_t smem_addr, const void* gptr) {
    asm volatile("cp.async.cg.shared.global [%0], [%1], 16;"
        :: "r"(smem_addr), "l"(gptr));
}
#define CP_COMMIT() asm volatile("cp.async.commit_group;" ::: "memory")
#define CP_WAIT1()  asm volatile("cp.async.wait_group 1;" ::: "memory")

// ---------------------------------------------------------------------------
// Conversion kernels
// ---------------------------------------------------------------------------
__global__ void conv_hilo_kernel(const float* __restrict__ in,
                                 __nv_bfloat16* __restrict__ hi,
                                 __nv_bfloat16* __restrict__ lo, int n4)
{
    int i = blockIdx.x * blockDim.x + threadIdx.x;
    if (i >= n4) return;
    float4 v = reinterpret_cast<const float4*>(in)[i];
    __nv_bfloat16 h0 = __float2bfloat16(v.x);
    __nv_bfloat16 h1 = __float2bfloat16(v.y);
    __nv_bfloat16 h2 = __float2bfloat16(v.z);
    __nv_bfloat16 h3 = __float2bfloat16(v.w);
    __nv_bfloat16 l0 = __float2bfloat16(v.x - __bfloat162float(h0));
    __nv_bfloat16 l1 = __float2bfloat16(v.y - __bfloat162float(h1));
    __nv_bfloat16 l2 = __float2bfloat16(v.z - __bfloat162float(h2));
    __nv_bfloat16 l3 = __float2bfloat16(v.w - __bfloat162float(h3));
    __nv_bfloat162* hp = reinterpret_cast<__nv_bfloat162*>(hi);
    __nv_bfloat162* lp = reinterpret_cast<__nv_bfloat162*>(lo);
    hp[2*i]   = __nv_bfloat162(h0, h1);
    hp[2*i+1] = __nv_bfloat162(h2, h3);
    lp[2*i]   = __nv_bfloat162(l0, l1);
    lp[2*i+1] = __nv_bfloat162(l2, l3);
}

// W[K][N] fp32 -> Wt_hi/Wt_lo [N][K] bf16 (transpose + split)
__global__ void wconv_kernel(const float* __restrict__ W,
                             __nv_bfloat16* __restrict__ th,
                             __nv_bfloat16* __restrict__ tl)
{
    __shared__ float t[32][33];
    int tx = threadIdx.x, ty = threadIdx.y;       // (32, 8)
    int n0 = blockIdx.x * 32, k0 = blockIdx.y * 32;
#pragma unroll
    for (int j = 0; j < 32; j += 8)
        t[ty + j][tx] = W[(long)(k0 + ty + j) * DM + n0 + tx];
    __syncthreads();
#pragma unroll
    for (int j = 0; j < 32; j += 8) {
        float x = t[tx][ty + j];
        long n = n0 + ty + j, k = k0 + tx;
        __nv_bfloat16 h = __float2bfloat16(x);
        th[n * DM + k] = h;
        tl[n * DM + k] = __float2bfloat16(x - __bfloat162float(h));
    }
}

// ---------------------------------------------------------------------------
// mma.sync bf16x3 GEMM with cp.async 3-stage pipeline.
// C[M,N] = (Ah+Al)[M,K] * ((Bh+Bl)[N,K])^T + bias
// If C != null: fp32 out. Else: bf16 hi/lo out (Oh/Ol).
// ---------------------------------------------------------------------------
#define GBM 128
#define GBN 128
#define GBK 32
#define NCHUNK (DM / GBK)          // 32
#define HTILE  16384               // 16KB (A or B) per stage
#define STAGEB (2 * HTILE)         // 32KB per stage
#define GEMM_SMEM (3 * STAGEB)     // 98304

__device__ __forceinline__ void gemm_load_stage(
    uint32_t sA, uint32_t sB,
    const __nv_bfloat16* __restrict__ Ah, const __nv_bfloat16* __restrict__ Al,
    const __nv_bfloat16* __restrict__ Bh, const __nv_bfloat16* __restrict__ Bl,
    long bm, long bn, int k0, int urow, int uc)
{
#pragma unroll
    for (int t = 0; t < 2; t++) {
        int row = urow + t * 64;
        const long go = (bm + row) * DM + k0 + uc * 8;
        const long gn = (bn + row) * DM + k0 + uc * 8;
        uint32_t offH = (uint32_t)(row * 128 + ((uc       ^ (row & 7)) << 4));
        uint32_t offL = (uint32_t)(row * 128 + (((uc + 4) ^ (row & 7)) << 4));
        cp_async16(sA + offH, Ah + go);
        cp_async16(sA + offL, Al + go);
        cp_async16(sB + offH, Bh + gn);
        cp_async16(sB + offL, Bl + gn);
    }
}

__global__ __launch_bounds__(256, 2) void gemm_tc_kernel(
    const __nv_bfloat16* __restrict__ Ah, const __nv_bfloat16* __restrict__ Al,
    const __nv_bfloat16* __restrict__ Bh, const __nv_bfloat16* __restrict__ Bl,
    const float* __restrict__ bias, float* __restrict__ C,
    __nv_bfloat16* __restrict__ Oh, __nv_bfloat16* __restrict__ Ol)
{
    extern __shared__ char gsm[];
    const uint32_t sbase = smem_to_u32(gsm);
    const int tid  = threadIdx.x;
    const int wid  = tid >> 5;
    const int lane = tid & 31;
    const int wm   = (wid >> 2) * 64;
    const int wn   = (wid & 3) * 32;
    const long bm  = (long)blockIdx.y * GBM;
    const long bn  = (long)blockIdx.x * GBN;

    const int urow = tid >> 2;
    const int uc   = tid & 3;

    float acc[4][4][4];
#pragma unroll
    for (int mi = 0; mi < 4; mi++)
#pragma unroll
        for (int ni = 0; ni < 4; ni++)
#pragma unroll
            for (int q = 0; q < 4; q++) acc[mi][ni][q] = 0.f;

    // Prologue: stages 0 and 1 in flight
    gemm_load_stage(sbase, sbase + HTILE, Ah, Al, Bh, Bl, bm, bn, 0, urow, uc);
    CP_COMMIT();
    gemm_load_stage(sbase + STAGEB, sbase + STAGEB + HTILE, Ah, Al, Bh, Bl, bm, bn, GBK, urow, uc);
    CP_COMMIT();

    for (int it = 0; it < NCHUNK; ++it) {
        CP_WAIT1();
        __syncthreads();

        const int nx = it + 2;
        if (nx < NCHUNK) {
            const uint32_t st = sbase + (nx % 3) * STAGEB;
            gemm_load_stage(st, st + HTILE, Ah, Al, Bh, Bl, bm, bn, nx * GBK, urow, uc);
        }
        CP_COMMIT();

        const uint32_t sA = sbase + (it % 3) * STAGEB;
        const uint32_t sB = sA + HTILE;

#pragma unroll
        for (int ks = 0; ks < 2; ks++) {
            uint32_t afh[4][4], afl[4][4];
#pragma unroll
            for (int mi = 0; mi < 4; mi++) {
                ldmA(afh[mi], sA, wm + mi * 16, ks * 2,     lane);
                ldmA(afl[mi], sA, wm + mi * 16, ks * 2 + 4, lane);
            }
            uint32_t bfh[4][2], bfl[4][2];
#pragma unroll
            for (int ni = 0; ni < 4; ni++) {
                ldmB(bfh[ni], sB, wn + ni * 8, ks * 2,     lane);
                ldmB(bfl[ni], sB, wn + ni * 8, ks * 2 + 4, lane);
            }
#pragma unroll
            for (int mi = 0; mi < 4; mi++)
#pragma unroll
                for (int ni = 0; ni < 4; ni++) {
                    mma16816(acc[mi][ni], afh[mi], bfh[ni]);
                    mma16816(acc[mi][ni], afh[mi], bfl[ni]);
                    mma16816(acc[mi][ni], afl[mi], bfh[ni]);
                }
        }
    }

    // Epilogue
#pragma unroll
    for (int mi = 0; mi < 4; mi++) {
#pragma unroll
        for (int ni = 0; ni < 4; ni++) {
            long r0  = bm + wm + mi * 16 + (lane >> 2);
            long col = bn + wn + ni * 8 + (lane & 3) * 2;
            float2 bv = *(const float2*)&bias[col];
            float2 v0, v1;
            v0.x = acc[mi][ni][0] + bv.x; v0.y = acc[mi][ni][1] + bv.y;
            v1.x = acc[mi][ni][2] + bv.x; v1.y = acc[mi][ni][3] + bv.y;
            if (C) {
                *(float2*)&C[r0 * DM + col]       = v0;
                *(float2*)&C[(r0 + 8) * DM + col] = v1;
            } else {
                uint32_t h0 = pack_bf16(v0.x, v0.y);
                uint32_t h1 = pack_bf16(v1.x, v1.y);
                float2 f0 = __bfloat1622float2(*reinterpret_cast<__nv_bfloat162*>(&h0));
                float2 f1 = __bfloat1622float2(*reinterpret_cast<__nv_bfloat162*>(&h1));
                uint32_t l0 = pack_bf16(v0.x - f0.x, v0.y - f0.y);
                uint32_t l1 = pack_bf16(v1.x - f1.x, v1.y - f1.y);
                *(uint32_t*)&Oh[r0 * DM + col]       = h0;
                *(uint32_t*)&Oh[(r0 + 8) * DM + col] = h1;
                *(uint32_t*)&Ol[r0 * DM + col]       = l0;
                *(uint32_t*)&Ol[(r0 + 8) * DM + col] = l1;
            }
        }
    }
}

// ---------------------------------------------------------------------------
// mma.sync flash attention with cp.async double-buffered K/V.
// grid=(SEQ/128, B*NH), 128 threads (4 warps). Q tile 128 rows resident.
// V consumed from natural [s,dm] layout via ldmatrix.trans. Output -> bf16 hi/lo.
// ---------------------------------------------------------------------------
#define SQH 0
#define SQL 16384
#define KVBASE 32768
#define KVSTG  32768          // per stage: KH 8K | KL 8K | VH 8K | VL 8K
#define ATTN_SMEM (KVBASE + 2 * KVSTG)   // 98304
#define SFC 0.18033688011112042f   // 0.125 * log2(e)

__device__ __forceinline__ void stsw(char* tile, int row, int c, uint4 v) {
    uint32_t off = (uint32_t)(row * 128 + ((c ^ (row & 7)) << 4));
    *reinterpret_cast<uint4*>(tile + off) = v;
}

__device__ __forceinline__ void attn_load_kv(
    uint32_t st,
    const __nv_bfloat16* __restrict__ Kh, const __nv_bfloat16* __restrict__ Kl,
    const __nv_bfloat16* __restrict__ Vh, const __nv_bfloat16* __restrict__ Vl,
    long kr, int hcol, int tid)
{
#pragma unroll
    for (int i = 0; i < 4; i++) {
        int idx = i * 128 + tid;
        int r = idx >> 3, c = idx & 7;
        long go = (kr + r) * DM + hcol + c * 8;
        uint32_t off = (uint32_t)(r * 128 + ((c ^ (r & 7)) << 4));
        cp_async16(st + off,          Kh + go);
        cp_async16(st + 8192 + off,   Kl + go);
        cp_async16(st + 16384 + off,  Vh + go);
        cp_async16(st + 24576 + off,  Vl + go);
    }
}

__global__ __launch_bounds__(128, 2) void attn_tc_kernel(
    const __nv_bfloat16* __restrict__ Qh, const __nv_bfloat16* __restrict__ Ql,
    const __nv_bfloat16* __restrict__ Kh, const __nv_bfloat16* __restrict__ Kl,
    const __nv_bfloat16* __restrict__ Vh, const __nv_bfloat16* __restrict__ Vl,
    __nv_bfloat16* __restrict__ Ohi, __nv_bfloat16* __restrict__ Olo)
{
    extern __shared__ char smc[];
    const uint32_t sb = smem_to_u32(smc);
    const int tid  = threadIdx.x;
    const int wid  = tid >> 5;
    const int lane = tid & 31;
    const int bh   = blockIdx.y;
    const int b    = bh >> 4;
    const int h    = bh & 15;
    const int q0   = blockIdx.x * 128;
    const int hcol = h * HD;

    const long qrow0 = (long)b * SEQ + q0;
    const long krow0 = (long)b * SEQ;

    // Prologue: stage 0 KV in flight
    attn_load_kv(sb + KVBASE, Kh, Kl, Vh, Vl, krow0, hcol, tid);
    CP_COMMIT();

    // Load Q tile (128 rows x 64 bf16 = 8 chunks/row), hi+lo (plain stores)
#pragma unroll
    for (int i = 0; i < 8; i++) {
        int idx = i * 128 + tid;
        int r = idx >> 3, c = idx & 7;
        long off = (qrow0 + r) * DM + hcol + c * 8;
        stsw(smc + SQH, r, c, *(const uint4*)(Qh + off));
        stsw(smc + SQL, r, c, *(const uint4*)(Ql + off));
    }

    float o[2][8][4];
    float mrow[2][2], lrow[2][2];
#pragma unroll
    for (int mi = 0; mi < 2; mi++) {
#pragma unroll
        for (int hf = 0; hf < 2; hf++) { mrow[mi][hf] = -INFINITY; lrow[mi][hf] = 0.f; }
#pragma unroll
        for (int ni = 0; ni < 8; ni++)
#pragma unroll
            for (int q = 0; q < 4; q++) o[mi][ni][q] = 0.f;
    }

    const int wm = wid * 32;

    for (int kt = 0; kt < SEQ / 64; ++kt) {
        // Prefetch next KV stage
        if (kt + 1 < SEQ / 64)
            attn_load_kv(sb + KVBASE + ((kt + 1) & 1) * KVSTG,
                         Kh, Kl, Vh, Vl, krow0 + (kt + 1) * 64, hcol, tid);
        CP_COMMIT();
        CP_WAIT1();          // stage kt complete
        __syncthreads();     // all warps see it (and Q on first iter)

        const uint32_t sKH = sb + KVBASE + (kt & 1) * KVSTG;
        const uint32_t sKL = sKH + 8192;
        const uint32_t sVH = sKH + 16384;
        const uint32_t sVL = sKH + 24576;

        // ---- S = Q K^T (3-term split) ----
        float s[2][8][4];
#pragma unroll
        for (int mi = 0; mi < 2; mi++)
#pragma unroll
            for (int ni = 0; ni < 8; ni++)
#pragma unroll
                for (int q = 0; q < 4; q++) s[mi][ni][q] = 0.f;

#pragma unroll
        for (int ks = 0; ks < 4; ks++) {
            uint32_t aH[2][4], aL[2][4];
#pragma unroll
            for (int mi = 0; mi < 2; mi++) {
                ldmA(aH[mi], sb + SQH, wm + mi * 16, ks * 2, lane);
                ldmA(aL[mi], sb + SQL, wm + mi * 16, ks * 2, lane);
            }
#pragma unroll
            for (int ni = 0; ni < 8; ni++) {
                uint32_t bh2[2], bl2[2];
                ldmB(bh2, sKH, ni * 8, ks * 2, lane);
                ldmB(bl2, sKL, ni * 8, ks * 2, lane);
#pragma unroll
                for (int mi = 0; mi < 2; mi++) {
                    mma16816(s[mi][ni], aH[mi], bh2);
                    mma16816(s[mi][ni], aH[mi], bl2);
                    mma16816(s[mi][ni], aL[mi], bh2);
                }
            }
        }

        // ---- online softmax ----
#pragma unroll
        for (int mi = 0; mi < 2; mi++) {
#pragma unroll
            for (int hf = 0; hf < 2; hf++) {
                float mx = -INFINITY;
#pragma unroll
                for (int ni = 0; ni < 8; ni++) {
                    mx = fmaxf(mx, s[mi][ni][hf * 2]);
                    mx = fmaxf(mx, s[mi][ni][hf * 2 + 1]);
                }
                mx = fmaxf(mx, __shfl_xor_sync(0xffffffffu, mx, 1));
                mx = fmaxf(mx, __shfl_xor_sync(0xffffffffu, mx, 2));
                float mnew = fmaxf(mrow[mi][hf], mx);
                float corr = ex2f_fast((mrow[mi][hf] - mnew) * SFC);
                mrow[mi][hf] = mnew;
                float nmc = -mnew * SFC;
                float rs = 0.f;
#pragma unroll
                for (int ni = 0; ni < 8; ni++) {
                    float p0 = ex2f_fast(fmaf(s[mi][ni][hf * 2],     SFC, nmc));
                    float p1 = ex2f_fast(fmaf(s[mi][ni][hf * 2 + 1], SFC, nmc));
                    s[mi][ni][hf * 2]     = p0;
                    s[mi][ni][hf * 2 + 1] = p1;
                    rs += p0 + p1;
                }
                rs += __shfl_xor_sync(0xffffffffu, rs, 1);
                rs += __shfl_xor_sync(0xffffffffu, rs, 2);
                lrow[mi][hf] = lrow[mi][hf] * corr + rs;
#pragma unroll
                for (int ni = 0; ni < 8; ni++) {
                    o[mi][ni][hf * 2]     *= corr;
                    o[mi][ni][hf * 2 + 1] *= corr;
                }
            }
        }

        // ---- O += P V (P split to bf16 hi/lo in registers; V via ldmatrix.trans) ----
#pragma unroll
        for (int ks = 0; ks < 4; ks++) {
            uint32_t aPh[2][4], aPl[2][4];
#pragma unroll
            for (int mi = 0; mi < 2; mi++) {
                const float* t0 = s[mi][2 * ks];
                const float* t1 = s[mi][2 * ks + 1];
                float vs[8] = {t0[0], t0[1], t0[2], t0[3], t1[0], t1[1], t1[2], t1[3]};
#pragma unroll
                for (int p = 0; p < 4; p++) {
                    uint32_t hb = pack_bf16(vs[2 * p], vs[2 * p + 1]);
                    aPh[mi][p] = hb;
                    float2 bk = __bfloat1622float2(*reinterpret_cast<__nv_bfloat162*>(&hb));
                    aPl[mi][p] = pack_bf16(vs[2 * p] - bk.x, vs[2 * p + 1] - bk.y);
                }
            }
#pragma unroll
            for (int ni = 0; ni < 8; ni++) {
                uint32_t bvh[2], bvl[2];
                ldmBt(bvh, sVH, ni, ks, lane);
                ldmBt(bvl, sVL, ni, ks, lane);
#pragma unroll
                for (int mi = 0; mi < 2; mi++) {
                    mma16816(o[mi][ni], aPh[mi], bvh);
                    mma16816(o[mi][ni], aPh[mi], bvl);
                    mma16816(o[mi][ni], aPl[mi], bvh);
                }
            }
        }
        __syncthreads();     // stage kt reads done before it is overwritten
    }

    // ---- epilogue: O / l -> bf16 hi/lo (A operand of output projection) ----
#pragma unroll
    for (int mi = 0; mi < 2; mi++) {
#pragma unroll
        for (int hf = 0; hf < 2; hf++) {
            float inv = 1.f / lrow[mi][hf];
            long row = qrow0 + wm + mi * 16 + hf * 8 + (lane >> 2);
#pragma unroll
            for (int ni = 0; ni < 8; ni++) {
                long col = hcol + ni * 8 + (lane & 3) * 2;
                float vx = o[mi][ni][hf * 2]     * inv;
                float vy = o[mi][ni][hf * 2 + 1] * inv;
                uint32_t hb = pack_bf16(vx, vy);
                float2 f = __bfloat1622float2(*reinterpret_cast<__nv_bfloat162*>(&hb));
                uint32_t lb = pack_bf16(vx - f.x, vy - f.y);
                *(uint32_t*)&Ohi[row * DM + col] = hb;
                *(uint32_t*)&Olo[row * DM + col] = lb;
            }
        }
    }
}

// ---------------------------------------------------------------------------
extern "C" void kernel_launch(void* const* d_in, const int* in_sizes, int n_in,
                              void* d_out, int out_size)
{
    const float* query = (const float*)d_in[0];
    const float* key_  = (const float*)d_in[1];
    const float* value = (const float*)d_in[2];
    const float* Wq    = (const float*)d_in[3];
    const float* bq    = (const float*)d_in[4];
    const float* Wk    = (const float*)d_in[5];
    const float* bk    = (const float*)d_in[6];
    const float* Wv    = (const float*)d_in[7];
    const float* bv    = (const float*)d_in[8];
    const float* Wo    = (const float*)d_in[9];
    const float* bo    = (const float*)d_in[10];

    __nv_bfloat16 *ah, *al, *wh, *wl, *qh, *ql, *kh, *kl, *vh, *vl;
    cudaGetSymbolAddress((void**)&ah,  g_Ah);
    cudaGetSymbolAddress((void**)&al,  g_Al);
    cudaGetSymbolAddress((void**)&wh,  g_Wh);
    cudaGetSymbolAddress((void**)&wl,  g_Wl);
    cudaGetSymbolAddress((void**)&qh,  g_Qh);
    cudaGetSymbolAddress((void**)&ql,  g_Ql);
    cudaGetSymbolAddress((void**)&kh,  g_Kh);
    cudaGetSymbolAddress((void**)&kl,  g_Kl);
    cudaGetSymbolAddress((void**)&vh,  g_Vh);
    cudaGetSymbolAddress((void**)&vl,  g_Vl);

    cudaFuncSetAttribute(gemm_tc_kernel,
                         cudaFuncAttributeMaxDynamicSharedMemorySize, GEMM_SMEM);
    cudaFuncSetAttribute(attn_tc_kernel,
                         cudaFuncAttributeMaxDynamicSharedMemorySize, ATTN_SMEM);

    const int n4 = MTOT * DM / 4;
    dim3 wgrid(DM / 32, DM / 32);
    dim3 wblk(32, 8);
    dim3 ggrid(DM / GBN, MTOT / GBM);

    // Q projection -> bf16 hi/lo
    wconv_kernel<<<wgrid, wblk>>>(Wq, wh, wl);
    conv_hilo_kernel<<<n4 / 256, 256>>>(query, ah, al, n4);
    gemm_tc_kernel<<<ggrid, 256, GEMM_SMEM>>>(ah, al, wh, wl, bq, nullptr, qh, ql);
    // K projection -> bf16 hi/lo
    wconv_kernel<<<wgrid, wblk>>>(Wk, wh, wl);
    conv_hilo_kernel<<<n4 / 256, 256>>>(key_, ah, al, n4);
    gemm_tc_kernel<<<ggrid, 256, GEMM_SMEM>>>(ah, al, wh, wl, bk, nullptr, kh, kl);
    // V projection -> bf16 hi/lo (natural [b,s,dm] layout)
    wconv_kernel<<<wgrid, wblk>>>(Wv, wh, wl);
    conv_hilo_kernel<<<n4 / 256, 256>>>(value, ah, al, n4);
    gemm_tc_kernel<<<ggrid, 256, GEMM_SMEM>>>(ah, al, wh, wl, bv, nullptr, vh, vl);

    // Attention -> bf16 hi/lo straight into out-projection A operand
    dim3 agrid(SEQ / 128, BATCH * NH);
    attn_tc_kernel<<<agrid, 128, ATTN_SMEM>>>(qh, ql, kh, kl, vh, vl, ah, al);

    // Output projection -> fp32 out
    wconv_kernel<<<wgrid, wblk>>>(Wo, wh, wl);
    gemm_tc_kernel<<<ggrid, 256, GEMM_SMEM>>>(ah, al, wh, wl, bo, (float*)d_out, nullptr, nullptr);
}